// round 3
// baseline (speedup 1.0000x reference)
#include <cuda_runtime.h>
#include <math.h>

#define Bc  64
#define Sc  512
#define Tc  256
#define Ec  512
#define Hc  512
#define KQc 256
#define Vc  1000
#define BH  (Bc*Hc)
#define NBLK 128
#define NTHR 256

// ---------------- device scratch (no runtime allocation allowed) ----------------
__device__ float g_k[Bc*Sc*KQc];        // K cache [B,S,KQ]
__device__ float g_v[Bc*Sc*Ec];         // V cache [B,S,E]
__device__ float g_emb1[Vc*4*Hc];       // per-token LSTM1 input-side gate preact (+b_ih1+b_hh1)
__device__ float g_h1[2*BH];
__device__ float g_c1[2*BH];
__device__ float g_h2[2*BH];
__device__ float g_c2[2*BH];
__device__ float g_ctx[Bc*Ec];
__device__ float g_hid[Bc*Hc];
__device__ float g_attn_dummy[Bc*Sc];

// ---------------- software grid barrier ----------------
__device__ volatile unsigned g_bar_gen;
__device__ unsigned g_bar_cnt;

__device__ __forceinline__ void gsync() {
    __syncthreads();
    if (threadIdx.x == 0) {
        unsigned gen = g_bar_gen;
        __threadfence();
        if (atomicAdd(&g_bar_cnt, 1u) == NBLK - 1) {
            g_bar_cnt = 0u;
            __threadfence();
            g_bar_gen = gen + 1u;
        } else {
            while (g_bar_gen == gen) { }
        }
        __threadfence();
    }
    __syncthreads();
}

// ---------------- shared memory union ----------------
struct __align__(16) Smem {
    union {
        struct { float As[16][68]; float Ws[16][68]; } gm;      // 8.7 KB
        struct { float x[64][68]; float h[64][68]; } lstm;      // 34.8 KB
        struct { float qh[512]; float qs[256]; float sc[512];
                 float red[8]; float red2[8]; } attn;           // 5.2 KB
        struct { float a[64][68]; } hid;                        // 17.4 KB
    } u;
};

__device__ __forceinline__ float dot4(float4 a, float4 w) {
    return a.x*w.x + a.y*w.y + a.z*w.z + a.w*w.w;
}

// ---------------- 64x64 GEMM tile: C = A[M,K] @ W[N,K]^T + b1 (+b2) ----------------
__device__ void gemm_tile(const float* __restrict__ A, const float* __restrict__ W,
                          const float* __restrict__ b1, const float* __restrict__ b2,
                          float* __restrict__ C, int M, int N, int K, int m0, int n0,
                          Smem* s)
{
    int tid = threadIdx.x;
    int tx = tid & 15, ty = tid >> 4;
    float acc[4][4] = {};
    for (int kb = 0; kb < K; kb += 16) {
        #pragma unroll
        for (int i = tid; i < 1024; i += NTHR) {
            int r = i >> 4, kk = i & 15;
            int ra = m0 + r; if (ra >= M) ra = M - 1;
            s->u.gm.As[kk][r] = A[(size_t)ra * K + kb + kk];
            s->u.gm.Ws[kk][r] = W[(size_t)(n0 + r) * K + kb + kk];
        }
        __syncthreads();
        #pragma unroll
        for (int kk = 0; kk < 16; kk++) {
            float4 a4 = *(const float4*)&s->u.gm.As[kk][ty * 4];
            float4 w4 = *(const float4*)&s->u.gm.Ws[kk][tx * 4];
            float ar[4] = {a4.x, a4.y, a4.z, a4.w};
            float wr[4] = {w4.x, w4.y, w4.z, w4.w};
            #pragma unroll
            for (int i = 0; i < 4; i++)
                #pragma unroll
                for (int j = 0; j < 4; j++)
                    acc[i][j] += ar[i] * wr[j];
        }
        __syncthreads();
    }
    #pragma unroll
    for (int i = 0; i < 4; i++) {
        int row = m0 + ty * 4 + i;
        if (row < M) {
            #pragma unroll
            for (int j = 0; j < 4; j++) {
                int col = n0 + tx * 4 + j;
                float v = acc[i][j] + b1[col];
                if (b2) v += b2[col];
                C[(size_t)row * N + col] = v;
            }
        }
    }
    __syncthreads();
}

// ---------------- LSTM phase (one step, one layer) ----------------
// block = j-tile of 4; thread = (b, jl). HASX: layer2 (x = h1_nxt); else layer1 (x from table)
template<bool HASX>
__device__ void lstm_phase(const float* __restrict__ hin, const float* __restrict__ cin,
                           float* __restrict__ hout, float* __restrict__ cout,
                           const float* __restrict__ xsrc,
                           const int* __restrict__ y, int t,
                           const float* __restrict__ Wih, const float* __restrict__ Whh,
                           const float* __restrict__ bih, const float* __restrict__ bhh,
                           Smem* s)
{
    int tid = threadIdx.x;
    int b = tid & 63, jl = tid >> 6;
    int j = blockIdx.x * 4 + jl;

    float ai, af, ag, ao;
    if (!HASX) {
        int tok = (t == 0) ? 0 : y[b * Tc + t - 1];
        const float* e = g_emb1 + (size_t)tok * (4 * Hc);
        ai = e[j]; af = e[512 + j]; ag = e[1024 + j]; ao = e[1536 + j];
    } else {
        ai = bih[j] + bhh[j];
        af = bih[512 + j] + bhh[512 + j];
        ag = bih[1024 + j] + bhh[1024 + j];
        ao = bih[1536 + j] + bhh[1536 + j];
    }

    const float* wh0 = Whh + (size_t)j * Hc;
    const float* wh1 = Whh + (size_t)(512 + j) * Hc;
    const float* wh2 = Whh + (size_t)(1024 + j) * Hc;
    const float* wh3 = Whh + (size_t)(1536 + j) * Hc;
    const float* wi0 = HASX ? Wih + (size_t)j * Hc : nullptr;
    const float* wi1 = HASX ? Wih + (size_t)(512 + j) * Hc : nullptr;
    const float* wi2 = HASX ? Wih + (size_t)(1024 + j) * Hc : nullptr;
    const float* wi3 = HASX ? Wih + (size_t)(1536 + j) * Hc : nullptr;

    for (int kb = 0; kb < Hc; kb += 64) {
        #pragma unroll
        for (int i = tid; i < 4096; i += NTHR) {
            int bb = i >> 6, kk = i & 63;
            s->u.lstm.h[bb][kk] = hin[bb * Hc + kb + kk];
            if (HASX) s->u.lstm.x[bb][kk] = xsrc[bb * Hc + kb + kk];
        }
        __syncthreads();
        #pragma unroll
        for (int kk = 0; kk < 64; kk += 4) {
            float4 hv = *(const float4*)&s->u.lstm.h[b][kk];
            ai += dot4(hv, *(const float4*)(wh0 + kb + kk));
            af += dot4(hv, *(const float4*)(wh1 + kb + kk));
            ag += dot4(hv, *(const float4*)(wh2 + kb + kk));
            ao += dot4(hv, *(const float4*)(wh3 + kb + kk));
            if (HASX) {
                float4 xv = *(const float4*)&s->u.lstm.x[b][kk];
                ai += dot4(xv, *(const float4*)(wi0 + kb + kk));
                af += dot4(xv, *(const float4*)(wi1 + kb + kk));
                ag += dot4(xv, *(const float4*)(wi2 + kb + kk));
                ao += dot4(xv, *(const float4*)(wi3 + kb + kk));
            }
        }
        __syncthreads();
    }

    float si = 1.f / (1.f + __expf(-ai));
    float sf = 1.f / (1.f + __expf(-af));
    float so = 1.f / (1.f + __expf(-ao));
    float cN = sf * cin[b * Hc + j] + si * tanhf(ag);
    float hN = so * tanhf(cN);
    hout[b * Hc + j] = hN;
    cout[b * Hc + j] = cN;
}

// ---------------- q + attention phase (one block per b; blocks >= 64 skip) ----------------
__device__ void qattn_phase(int b, const float* __restrict__ h2n,
                            const float* __restrict__ Wq, const float* __restrict__ bq,
                            float* __restrict__ attn_out, Smem* s)
{
    int tid = threadIdx.x, warp = tid >> 5, lane = tid & 31;

    s->u.attn.qh[tid]       = h2n[b * Hc + tid];
    s->u.attn.qh[256 + tid] = h2n[b * Hc + 256 + tid];
    __syncthreads();

    // q[j] = h2[b] . Wq[j] + bq[j]
    for (int jj = warp; jj < KQc; jj += 8) {
        const float* wr = Wq + (size_t)jj * Hc;
        float sum = 0.f;
        #pragma unroll
        for (int u = 0; u < 16; u++) sum += s->u.attn.qh[lane + 32 * u] * wr[lane + 32 * u];
        #pragma unroll
        for (int o = 16; o; o >>= 1) sum += __shfl_down_sync(~0u, sum, o);
        if (lane == 0) s->u.attn.qs[jj] = sum + bq[jj];
    }
    __syncthreads();

    // scores
    for (int ss = warp; ss < Sc; ss += 8) {
        const float* kr = g_k + ((size_t)b * Sc + ss) * KQc;
        float sum = 0.f;
        #pragma unroll
        for (int u = 0; u < 8; u++) sum += s->u.attn.qs[lane + 32 * u] * kr[lane + 32 * u];
        #pragma unroll
        for (int o = 16; o; o >>= 1) sum += __shfl_down_sync(~0u, sum, o);
        if (lane == 0) s->u.attn.sc[ss] = sum * 0.0625f;  // 1/sqrt(256)
    }
    __syncthreads();

    // softmax over 512 (each thread holds 2)
    float v0 = s->u.attn.sc[tid], v1 = s->u.attn.sc[tid + 256];
    float m = fmaxf(v0, v1);
    #pragma unroll
    for (int o = 16; o; o >>= 1) m = fmaxf(m, __shfl_xor_sync(~0u, m, o));
    if (lane == 0) s->u.attn.red[warp] = m;
    __syncthreads();
    float mm = s->u.attn.red[0];
    #pragma unroll
    for (int w = 1; w < 8; w++) mm = fmaxf(mm, s->u.attn.red[w]);
    float e0 = __expf(v0 - mm), e1 = __expf(v1 - mm);
    float ssum = e0 + e1;
    #pragma unroll
    for (int o = 16; o; o >>= 1) ssum += __shfl_xor_sync(~0u, ssum, o);
    if (lane == 0) s->u.attn.red2[warp] = ssum;
    __syncthreads();
    float Z = 0.f;
    #pragma unroll
    for (int w = 0; w < 8; w++) Z += s->u.attn.red2[w];
    float inv = 1.f / Z;
    float p0 = e0 * inv, p1 = e1 * inv;
    s->u.attn.sc[tid] = p0;
    s->u.attn.sc[tid + 256] = p1;
    attn_out[tid] = p0;
    attn_out[tid + 256] = p1;
    __syncthreads();

    // ctx[b, e] = sum_s p[s] * V[b,s,e]; thread covers e pair
    int e = tid * 2;
    const float* vb = g_v + (size_t)b * Sc * Ec + e;
    float ax = 0.f, ay = 0.f;
    #pragma unroll 8
    for (int ss = 0; ss < Sc; ss++) {
        float p = s->u.attn.sc[ss];
        float2 vv = *(const float2*)(vb + (size_t)ss * Ec);
        ax += p * vv.x; ay += p * vv.y;
    }
    g_ctx[b * Ec + e]     = ax;
    g_ctx[b * Ec + e + 1] = ay;
}

// ---------------- hid = relu([h2|ctx] @ W1^T + b1) ----------------
__device__ void hid_phase(const float* __restrict__ h2n,
                          const float* __restrict__ W1, const float* __restrict__ b1, Smem* s)
{
    int tid = threadIdx.x;
    int b = tid & 63, jl = tid >> 6;
    int j = blockIdx.x * 4 + jl;
    const float* wr = W1 + (size_t)j * (Hc + Ec);
    float acc = b1[j];
    for (int kb = 0; kb < Hc + Ec; kb += 64) {
        #pragma unroll
        for (int i = tid; i < 4096; i += NTHR) {
            int bb = i >> 6, kk = i & 63, kg = kb + kk;
            s->u.hid.a[bb][kk] = (kg < Hc) ? h2n[bb * Hc + kg] : g_ctx[bb * Ec + kg - Hc];
        }
        __syncthreads();
        #pragma unroll
        for (int kk = 0; kk < 64; kk += 4) {
            float4 a4 = *(const float4*)&s->u.hid.a[b][kk];
            acc += dot4(a4, *(const float4*)(wr + kb + kk));
        }
        __syncthreads();
    }
    g_hid[b * Hc + j] = fmaxf(acc, 0.f);
}

// ---------------- logits = hid @ W_emb^T + b_cls ----------------
__device__ void logits_phase(const float* __restrict__ Wemb, const float* __restrict__ bcls,
                             float* __restrict__ outL, int t, Smem* s)
{
    int tid = threadIdx.x;
    int b = tid & 63, jl = tid >> 6;
    for (int tile = blockIdx.x; tile < Vc / 4; tile += NBLK) {   // 250 tiles
        int j = tile * 4 + jl;
        const float* wr = Wemb + (size_t)j * Hc;
        float acc = bcls[j];
        for (int kb = 0; kb < Hc; kb += 64) {
            #pragma unroll
            for (int i = tid; i < 4096; i += NTHR) {
                int bb = i >> 6, kk = i & 63;
                s->u.hid.a[bb][kk] = g_hid[bb * Hc + kb + kk];
            }
            __syncthreads();
            #pragma unroll
            for (int kk = 0; kk < 64; kk += 4) {
                float4 a4 = *(const float4*)&s->u.hid.a[b][kk];
                acc += dot4(a4, *(const float4*)(wr + kb + kk));
            }
            __syncthreads();
        }
        outL[((size_t)b * Tc + t) * Vc + j] = acc;
    }
}

// ---------------- persistent kernel ----------------
__global__ void __launch_bounds__(NTHR, 1)
decoder_kernel(const float* __restrict__ enc, const int* __restrict__ y,
               const float* __restrict__ Wemb,
               const float* __restrict__ Wih1, const float* __restrict__ bih1,
               const float* __restrict__ Whh1, const float* __restrict__ bhh1,
               const float* __restrict__ Wih2, const float* __restrict__ bih2,
               const float* __restrict__ Whh2, const float* __restrict__ bhh2,
               const float* __restrict__ Wq,  const float* __restrict__ bq,
               const float* __restrict__ Wk,  const float* __restrict__ bk,
               const float* __restrict__ Wv,  const float* __restrict__ bv,
               const float* __restrict__ W1,  const float* __restrict__ b1,
               const float* __restrict__ bcls,
               float* __restrict__ outL, float* __restrict__ attnB,
               int attnBS, int attnTS)
{
    __shared__ Smem s;
    int tid = threadIdx.x;

    // zero initial state (parity-0 buffers)
    for (int i = blockIdx.x * NTHR + tid; i < BH; i += NBLK * NTHR) {
        g_h1[i] = 0.f; g_c1[i] = 0.f; g_h2[i] = 0.f; g_c2[i] = 0.f;
    }
    gsync();

    // precompute: K cache, V cache, per-token LSTM1 input-side table
    {
        const int nKt = (Bc * Sc / 64) * (KQc / 64);   // 2048
        const int nVt = (Bc * Sc / 64) * (Ec / 64);    // 4096
        const int nEt = 16 * (4 * Hc / 64);            // 512 (M=1000 -> 16 row tiles)
        for (int idx = blockIdx.x; idx < nKt + nVt + nEt; idx += NBLK) {
            if (idx < nKt) {
                int m0 = (idx / (KQc / 64)) * 64, n0 = (idx % (KQc / 64)) * 64;
                gemm_tile(enc, Wk, bk, nullptr, g_k, Bc * Sc, KQc, Ec, m0, n0, &s);
            } else if (idx < nKt + nVt) {
                int i2 = idx - nKt;
                int m0 = (i2 / (Ec / 64)) * 64, n0 = (i2 % (Ec / 64)) * 64;
                gemm_tile(enc, Wv, bv, nullptr, g_v, Bc * Sc, Ec, Ec, m0, n0, &s);
            } else {
                int i2 = idx - nKt - nVt;
                int m0 = (i2 / 32) * 64, n0 = (i2 % 32) * 64;
                gemm_tile(Wemb, Wih1, bih1, bhh1, g_emb1, Vc, 4 * Hc, Hc, m0, n0, &s);
            }
        }
    }
    gsync();

    for (int t = 0; t < Tc; t++) {
        int cur = t & 1, nxt = cur ^ 1;

        lstm_phase<false>(g_h1 + cur * BH, g_c1 + cur * BH,
                          g_h1 + nxt * BH, g_c1 + nxt * BH,
                          nullptr, y, t, nullptr, Whh1, nullptr, nullptr, &s);
        gsync();

        lstm_phase<true>(g_h2 + cur * BH, g_c2 + cur * BH,
                         g_h2 + nxt * BH, g_c2 + nxt * BH,
                         g_h1 + nxt * BH, y, t, Wih2, Whh2, bih2, bhh2, &s);
        gsync();

        if (blockIdx.x < Bc)
            qattn_phase(blockIdx.x, g_h2 + nxt * BH, Wq, bq,
                        attnB + (size_t)blockIdx.x * attnBS + (size_t)t * attnTS, &s);
        gsync();

        hid_phase(g_h2 + nxt * BH, W1, b1, &s);
        gsync();

        logits_phase(Wemb, bcls, outL, t, &s);
        // no barrier needed: next step's LSTM1 touches only h1/c1/table (disjoint from logits)
    }
}

// ---------------- launch ----------------
extern "C" void kernel_launch(void* const* d_in, const int* in_sizes, int n_in,
                              void* d_out, int out_size) {
    const float* enc   = (const float*)d_in[0];
    const int*   y     = (const int*)  d_in[1];
    const float* Wemb  = (const float*)d_in[2];
    const float* Wih1  = (const float*)d_in[3];
    const float* bih1  = (const float*)d_in[4];
    const float* Whh1  = (const float*)d_in[5];
    const float* bhh1  = (const float*)d_in[6];
    const float* Wih2  = (const float*)d_in[7];
    const float* bih2  = (const float*)d_in[8];
    const float* Whh2  = (const float*)d_in[9];
    const float* bhh2  = (const float*)d_in[10];
    const float* Wq    = (const float*)d_in[11];
    const float* bq    = (const float*)d_in[12];
    const float* Wk    = (const float*)d_in[13];
    const float* bk    = (const float*)d_in[14];
    const float* Wv    = (const float*)d_in[15];
    const float* bv    = (const float*)d_in[16];
    const float* W1    = (const float*)d_in[17];
    const float* b1    = (const float*)d_in[18];
    const float* bcls  = (const float*)d_in[19];

    float* outL = (float*)d_out;
    long long need = (long long)Bc * Tc * Vc + (long long)Bc * Tc * Sc;

    float* attnB; int attnBS, attnTS;
    if ((long long)out_size >= need) {
        attnB = outL + (size_t)Bc * Tc * Vc;
        attnBS = Tc * Sc; attnTS = Sc;
    } else {
        cudaGetSymbolAddress((void**)&attnB, g_attn_dummy);
        attnBS = Sc; attnTS = 0;
    }

    decoder_kernel<<<NBLK, NTHR>>>(enc, y, Wemb, Wih1, bih1, Whh1, bhh1,
                                   Wih2, bih2, Whh2, bhh2, Wq, bq, Wk, bk,
                                   Wv, bv, W1, b1, bcls, outL, attnB, attnBS, attnTS);
}

// round 4
// speedup vs baseline: 1.9560x; 1.9560x over previous
#include <cuda_runtime.h>
#include <cuda_bf16.h>
#include <math.h>

#define Bc  64
#define Sc  512
#define Tc  256
#define Ec  512
#define Hc  512
#define KQc 256
#define Vc  1000
#define BH  (Bc*Hc)
#define NBLK 128
#define NTHR 256

// ---------------- device scratch ----------------
__device__ __nv_bfloat16 g_kbf[(size_t)Bc*Sc*KQc];   // K cache bf16 [B*S, KQ]
__device__ __nv_bfloat16 g_vbf[(size_t)Bc*Sc*Ec];    // V cache bf16 [B*S, E]
__device__ __nv_bfloat16 g_wqbf[KQc*Hc];             // Wq bf16
__device__ float g_emb1[(size_t)Vc*4*Hc];            // token -> LSTM1 x-side gate preact (+biases)
__device__ float g_h1[2*BH], g_c1[2*BH], g_h2[2*BH], g_c2[2*BH];
__device__ float g_ctx[Bc*Ec];
__device__ float g_hidA[Bc*Hc], g_hidB[Bc*Hc];
__device__ float g_attn_dummy[Bc*Sc];

// ---------------- software grid barrier ----------------
__device__ volatile unsigned g_bar_gen;
__device__ unsigned g_bar_cnt;

__device__ __forceinline__ void gsync() {
    __syncthreads();
    if (threadIdx.x == 0) {
        unsigned gen = g_bar_gen;
        __threadfence();
        if (atomicAdd(&g_bar_cnt, 1u) == NBLK - 1) {
            g_bar_cnt = 0u;
            __threadfence();
            g_bar_gen = gen + 1u;
        } else {
            while (g_bar_gen == gen) { }
        }
        __threadfence();
    }
    __syncthreads();
}

// ---------------- shared memory ----------------
struct __align__(16) Smem {
    union {
        struct { float As[16][68]; float Ws[16][68]; } gm;                     // precompute tiles
        struct { float As[64][68]; float Ws[16][68]; float red[16][68]; } ph;  // step GEMM phases
        struct { float qh[512]; float qs[256]; float sc[512];
                 float red[8]; float red2[8]; } at;                            // attention
    } u;
};

// ---------------- staging helpers ----------------
__device__ __forceinline__ void stageA(const float* __restrict__ A, int ldA, int kb, Smem* s) {
    int t = threadIdx.x;
    #pragma unroll
    for (int u2 = 0; u2 < 4; u2++) {
        int idx = t + u2 * NTHR;                 // 1024 float4 units = 64 rows x 16
        int row = idx >> 4, c4 = idx & 15;
        *(float4*)&s->u.ph.As[row][c4 * 4] =
            *(const float4*)&A[(size_t)row * ldA + kb + c4 * 4];
    }
}

template<int TN, int LSTMMAP>
__device__ __forceinline__ void stageW(const float* __restrict__ W, int ldW, int kb, int tile,
                                       Smem* s) {
    int t = threadIdx.x;
    if (t < TN * 16) {
        int r = t >> 4, c4 = t & 15;
        int row = LSTMMAP ? ((r >> 2) * Hc + tile * 4 + (r & 3)) : (tile * TN + r);
        *(float4*)&s->u.ph.Ws[r][c4 * 4] =
            *(const float4*)&W[(size_t)row * ldW + kb + c4 * 4];
    }
}

template<int TN>
__device__ __forceinline__ void mm_step(float* acc, Smem* s) {
    const int BP = 64 * TN / NTHR;               // outputs (b's) per thread
    int t = threadIdx.x;
    int r = t % TN, g = t / TN;
    int b0 = g * BP;
    #pragma unroll
    for (int kk = 0; kk < 64; kk += 4) {
        float4 w = *(const float4*)&s->u.ph.Ws[r][kk];
        #pragma unroll
        for (int i = 0; i < BP; i++) {
            float4 a = *(const float4*)&s->u.ph.As[b0 + i][kk];
            acc[i] += a.x * w.x + a.y * w.y + a.z * w.z + a.w * w.w;
        }
    }
}

template<int TN, int LSTMMAP>
__device__ void gemm_block(float* acc, const float* __restrict__ A, int ldA,
                           const float* __restrict__ W, int ldW, int K, int tile, Smem* s) {
    for (int kb = 0; kb < K; kb += 64) {
        __syncthreads();
        stageA(A, ldA, kb, s);
        stageW<TN, LSTMMAP>(W, ldW, kb, tile, s);
        __syncthreads();
        mm_step<TN>(acc, s);
    }
}

// ---------------- LSTM phase ----------------
template<bool HASX>
__device__ void lstm_phase(const float* __restrict__ hin, const float* __restrict__ cin,
                           float* __restrict__ hout, float* __restrict__ cout,
                           const float* __restrict__ xsrc, const int* __restrict__ y, int t,
                           const float* __restrict__ Wih, const float* __restrict__ Whh,
                           const float* __restrict__ bih, const float* __restrict__ bhh,
                           Smem* s) {
    int tile = blockIdx.x;                       // j-quad tile: j = tile*4 + jj
    float acc[4] = {0.f, 0.f, 0.f, 0.f};
    gemm_block<16, 1>(acc, hin, Hc, Whh, Hc, Hc, tile, s);
    if (HASX) gemm_block<16, 1>(acc, xsrc, Hc, Wih, Hc, Hc, tile, s);

    {   // scatter accumulators: red[r][b], r = g*4+jj
        int t0 = threadIdx.x;
        int r = t0 & 15, g = t0 >> 4, b0 = g * 4;
        __syncthreads();
        #pragma unroll
        for (int i = 0; i < 4; i++) s->u.ph.red[r][b0 + i] = acc[i];
        __syncthreads();
    }
    int u = threadIdx.x;
    int jj = u & 3, b = u >> 2;
    int j = tile * 4 + jj;
    float pi = s->u.ph.red[0 * 4 + jj][b];
    float pf = s->u.ph.red[1 * 4 + jj][b];
    float pg = s->u.ph.red[2 * 4 + jj][b];
    float po = s->u.ph.red[3 * 4 + jj][b];
    if (!HASX) {
        int tok = (t == 0) ? 0 : y[b * Tc + t - 1];
        const float* e = g_emb1 + (size_t)tok * (4 * Hc);
        pi += e[j]; pf += e[Hc + j]; pg += e[2 * Hc + j]; po += e[3 * Hc + j];
    } else {
        pi += bih[j]          + bhh[j];
        pf += bih[Hc + j]     + bhh[Hc + j];
        pg += bih[2 * Hc + j] + bhh[2 * Hc + j];
        po += bih[3 * Hc + j] + bhh[3 * Hc + j];
    }
    float si = 1.f / (1.f + __expf(-pi));
    float sf = 1.f / (1.f + __expf(-pf));
    float so = 1.f / (1.f + __expf(-po));
    float cN = sf * cin[b * Hc + j] + si * tanhf(pg);
    float hN = so * tanhf(cN);
    hout[b * Hc + j] = hN;
    cout[b * Hc + j] = cN;
}

// ---------------- q + attention (blocks 0..63: b = blockIdx) ----------------
__device__ void qattn_phase(int b, const float* __restrict__ h2n,
                            const float* __restrict__ bq,
                            float* __restrict__ attn_out, Smem* s) {
    int tid = threadIdx.x, warp = tid >> 5, lane = tid & 31;

    s->u.at.qh[tid]       = h2n[b * Hc + tid];
    s->u.at.qh[256 + tid] = h2n[b * Hc + 256 + tid];
    __syncthreads();

    // hoist this lane's 16 h2 values (conflicted LDS once, reused 32x)
    float hr[16];
    #pragma unroll
    for (int u2 = 0; u2 < 16; u2++) hr[u2] = s->u.at.qh[lane * 16 + u2];

    // q[j] = h2[b] . Wq_bf[j] + bq[j]
    for (int j = warp; j < KQc; j += 8) {
        const __nv_bfloat16* wr = g_wqbf + (size_t)j * Hc + lane * 16;
        float sum = 0.f;
        #pragma unroll
        for (int h8 = 0; h8 < 2; h8++) {
            uint4 pk = *(const uint4*)(wr + h8 * 8);
            const __nv_bfloat162* p2 = (const __nv_bfloat162*)&pk;
            #pragma unroll
            for (int q2 = 0; q2 < 4; q2++) {
                float2 wf = __bfloat1622float2(p2[q2]);
                sum += hr[h8 * 8 + q2 * 2] * wf.x + hr[h8 * 8 + q2 * 2 + 1] * wf.y;
            }
        }
        #pragma unroll
        for (int o = 16; o; o >>= 1) sum += __shfl_down_sync(~0u, sum, o);
        if (lane == 0) s->u.at.qs[j] = sum + bq[j];
    }
    __syncthreads();

    // hoist this lane's 8 q values
    float qr[8];
    #pragma unroll
    for (int u2 = 0; u2 < 8; u2++) qr[u2] = s->u.at.qs[lane * 8 + u2];

    // scores
    for (int ss = warp; ss < Sc; ss += 8) {
        const __nv_bfloat16* kr = g_kbf + ((size_t)b * Sc + ss) * KQc + lane * 8;
        uint4 pk = *(const uint4*)kr;
        const __nv_bfloat162* p2 = (const __nv_bfloat162*)&pk;
        float sum = 0.f;
        #pragma unroll
        for (int q2 = 0; q2 < 4; q2++) {
            float2 kf = __bfloat1622float2(p2[q2]);
            sum += qr[q2 * 2] * kf.x + qr[q2 * 2 + 1] * kf.y;
        }
        #pragma unroll
        for (int o = 16; o; o >>= 1) sum += __shfl_down_sync(~0u, sum, o);
        if (lane == 0) s->u.at.sc[ss] = sum * 0.0625f;      // 1/sqrt(256)
    }
    __syncthreads();

    // softmax over 512 (2 per thread)
    float v0 = s->u.at.sc[tid], v1 = s->u.at.sc[tid + 256];
    float m = fmaxf(v0, v1);
    #pragma unroll
    for (int o = 16; o; o >>= 1) m = fmaxf(m, __shfl_xor_sync(~0u, m, o));
    if (lane == 0) s->u.at.red[warp] = m;
    __syncthreads();
    float mm = s->u.at.red[0];
    #pragma unroll
    for (int w = 1; w < 8; w++) mm = fmaxf(mm, s->u.at.red[w]);
    float e0 = __expf(v0 - mm), e1 = __expf(v1 - mm);
    float ssum = e0 + e1;
    #pragma unroll
    for (int o = 16; o; o >>= 1) ssum += __shfl_xor_sync(~0u, ssum, o);
    if (lane == 0) s->u.at.red2[warp] = ssum;
    __syncthreads();
    float Z = 0.f;
    #pragma unroll
    for (int w = 0; w < 8; w++) Z += s->u.at.red2[w];
    float inv = 1.f / Z;
    float p0 = e0 * inv, p1 = e1 * inv;
    s->u.at.sc[tid] = p0;
    s->u.at.sc[tid + 256] = p1;
    attn_out[tid] = p0;
    attn_out[tid + 256] = p1;
    __syncthreads();

    // ctx[b,e] = sum_s p[s] * V[b,s,e]; thread owns e-pair
    int e = tid * 2;
    const __nv_bfloat16* vb = g_vbf + (size_t)b * Sc * Ec + e;
    float ax = 0.f, ay = 0.f;
    #pragma unroll 8
    for (int ss2 = 0; ss2 < Sc; ss2++) {
        float p = s->u.at.sc[ss2];
        float2 vv = __bfloat1622float2(*(const __nv_bfloat162*)(vb + (size_t)ss2 * Ec));
        ax += p * vv.x; ay += p * vv.y;
    }
    g_ctx[b * Ec + e]     = ax;
    g_ctx[b * Ec + e + 1] = ay;
}

// ---------------- hid partials: A-part (h2 @ W1[:, :512]) and B-part (ctx @ W1[:, 512:]) ----------------
__device__ void hid_phase(const float* __restrict__ h2n, const float* __restrict__ W1,
                          const float* __restrict__ b1, Smem* s) {
    int bi = blockIdx.x;
    int part = bi >> 6;                          // 0: h2 part, 1: ctx part
    int tile = bi & 63;                          // N-tile of 8
    float acc[2] = {0.f, 0.f};
    const float* A = part ? g_ctx : h2n;
    const float* W = W1 + (part ? Ec : 0);
    gemm_block<8, 0>(acc, A, Hc, W, Hc + Ec, Hc, tile, s);
    int t0 = threadIdx.x;
    int r = t0 & 7, g = t0 >> 3;
    float* outp = part ? g_hidB : g_hidA;
    int j = tile * 8 + r;
    #pragma unroll
    for (int i = 0; i < 2; i++) {
        float v = acc[i];
        if (!part) v += b1[j];
        outp[(size_t)(g * 2 + i) * Hc + j] = v;
    }
}

// ---------------- logits = relu(hidA+hidB) @ W_emb^T + b_cls ----------------
__device__ void logits_phase(const float* __restrict__ Wemb, const float* __restrict__ bcls,
                             float* __restrict__ outL, int t, Smem* s) {
    int tile = blockIdx.x;
    if (tile >= Vc / 8) return;                  // 125 tiles
    float acc[2] = {0.f, 0.f};
    for (int kb = 0; kb < Hc; kb += 64) {
        __syncthreads();
        {
            int tt = threadIdx.x;
            #pragma unroll
            for (int u2 = 0; u2 < 4; u2++) {
                int idx = tt + u2 * NTHR;
                int row = idx >> 4, c4 = idx & 15;
                float4 a = *(const float4*)&g_hidA[(size_t)row * Hc + kb + c4 * 4];
                float4 bb = *(const float4*)&g_hidB[(size_t)row * Hc + kb + c4 * 4];
                float4 vv;
                vv.x = fmaxf(a.x + bb.x, 0.f);
                vv.y = fmaxf(a.y + bb.y, 0.f);
                vv.z = fmaxf(a.z + bb.z, 0.f);
                vv.w = fmaxf(a.w + bb.w, 0.f);
                *(float4*)&s->u.ph.As[row][c4 * 4] = vv;
            }
            stageW<8, 0>(Wemb, Hc, kb, tile, s);
        }
        __syncthreads();
        mm_step<8>(acc, s);
    }
    int t0 = threadIdx.x;
    int r = t0 & 7, g = t0 >> 3;
    int j = tile * 8 + r;
    #pragma unroll
    for (int i = 0; i < 2; i++) {
        int b = g * 2 + i;
        outL[((size_t)b * Tc + t) * Vc + j] = acc[i] + bcls[j];
    }
}

// ---------------- precompute 64x64 GEMM tile ----------------
__device__ __forceinline__ void storeC(float* C, size_t idx, float v) { C[idx] = v; }
__device__ __forceinline__ void storeC(__nv_bfloat16* C, size_t idx, float v) {
    C[idx] = __float2bfloat16(v);
}

template<class OUT>
__device__ void gemm_tile(const float* __restrict__ A, const float* __restrict__ W,
                          const float* __restrict__ b1, const float* __restrict__ b2,
                          OUT* __restrict__ C, int M, int N, int K, int m0, int n0, Smem* s) {
    int tid = threadIdx.x;
    int tx = tid & 15, ty = tid >> 4;
    float acc[4][4] = {};
    for (int kb = 0; kb < K; kb += 16) {
        __syncthreads();
        #pragma unroll
        for (int i = tid; i < 1024; i += NTHR) {
            int r = i >> 4, kk = i & 15;
            int ra = m0 + r; if (ra >= M) ra = M - 1;
            s->u.gm.As[kk][r] = A[(size_t)ra * K + kb + kk];
            s->u.gm.Ws[kk][r] = W[(size_t)(n0 + r) * K + kb + kk];
        }
        __syncthreads();
        #pragma unroll
        for (int kk = 0; kk < 16; kk++) {
            float4 a4 = *(const float4*)&s->u.gm.As[kk][ty * 4];
            float4 w4 = *(const float4*)&s->u.gm.Ws[kk][tx * 4];
            float ar[4] = {a4.x, a4.y, a4.z, a4.w};
            float wr[4] = {w4.x, w4.y, w4.z, w4.w};
            #pragma unroll
            for (int i = 0; i < 4; i++)
                #pragma unroll
                for (int j = 0; j < 4; j++)
                    acc[i][j] += ar[i] * wr[j];
        }
    }
    __syncthreads();
    #pragma unroll
    for (int i = 0; i < 4; i++) {
        int row = m0 + ty * 4 + i;
        if (row < M) {
            #pragma unroll
            for (int j = 0; j < 4; j++) {
                int col = n0 + tx * 4 + j;
                float v = acc[i][j] + b1[col];
                if (b2) v += b2[col];
                storeC(C, (size_t)row * N + col, v);
            }
        }
    }
}

// ---------------- persistent kernel ----------------
__global__ void __launch_bounds__(NTHR, 1)
decoder_kernel(const float* __restrict__ enc, const int* __restrict__ y,
               const float* __restrict__ Wemb,
               const float* __restrict__ Wih1, const float* __restrict__ bih1,
               const float* __restrict__ Whh1, const float* __restrict__ bhh1,
               const float* __restrict__ Wih2, const float* __restrict__ bih2,
               const float* __restrict__ Whh2, const float* __restrict__ bhh2,
               const float* __restrict__ Wq,  const float* __restrict__ bq,
               const float* __restrict__ Wk,  const float* __restrict__ bk,
               const float* __restrict__ Wv,  const float* __restrict__ bv,
               const float* __restrict__ W1,  const float* __restrict__ b1,
               const float* __restrict__ bcls,
               float* __restrict__ outL, float* __restrict__ attnB,
               int attnBS, int attnTS)
{
    __shared__ Smem s;
    int tid = threadIdx.x;

    // zero initial state (parity-0) + Wq bf16 copy
    for (int i = blockIdx.x * NTHR + tid; i < BH; i += NBLK * NTHR) {
        g_h1[i] = 0.f; g_c1[i] = 0.f; g_h2[i] = 0.f; g_c2[i] = 0.f;
    }
    for (int i = blockIdx.x * NTHR + tid; i < KQc * Hc; i += NBLK * NTHR)
        g_wqbf[i] = __float2bfloat16(Wq[i]);
    gsync();

    // precompute: K cache (bf16), V cache (bf16), LSTM1 x-side table (fp32)
    {
        const int nKt = (Bc * Sc / 64) * (KQc / 64);   // 2048
        const int nVt = (Bc * Sc / 64) * (Ec / 64);    // 4096
        const int nEt = 16 * (4 * Hc / 64);            // 512
        for (int idx = blockIdx.x; idx < nKt + nVt + nEt; idx += NBLK) {
            if (idx < nKt) {
                int m0 = (idx / (KQc / 64)) * 64, n0 = (idx % (KQc / 64)) * 64;
                gemm_tile(enc, Wk, bk, (const float*)0, g_kbf, Bc * Sc, KQc, Ec, m0, n0, &s);
            } else if (idx < nKt + nVt) {
                int i2 = idx - nKt;
                int m0 = (i2 / (Ec / 64)) * 64, n0 = (i2 % (Ec / 64)) * 64;
                gemm_tile(enc, Wv, bv, (const float*)0, g_vbf, Bc * Sc, Ec, Ec, m0, n0, &s);
            } else {
                int i2 = idx - nKt - nVt;
                int m0 = (i2 / 32) * 64, n0 = (i2 % 32) * 64;
                gemm_tile(Wemb, Wih1, bih1, bhh1, g_emb1, Vc, 4 * Hc, Hc, m0, n0, &s);
            }
        }
    }
    gsync();

    for (int t = 0; t < Tc; t++) {
        int cur = t & 1, nxt = cur ^ 1;

        lstm_phase<false>(g_h1 + cur * BH, g_c1 + cur * BH,
                          g_h1 + nxt * BH, g_c1 + nxt * BH,
                          (const float*)0, y, t, (const float*)0, Whh1,
                          (const float*)0, (const float*)0, &s);
        gsync();

        lstm_phase<true>(g_h2 + cur * BH, g_c2 + cur * BH,
                         g_h2 + nxt * BH, g_c2 + nxt * BH,
                         g_h1 + nxt * BH, y, t, Wih2, Whh2, bih2, bhh2, &s);
        gsync();

        if (blockIdx.x < Bc)
            qattn_phase(blockIdx.x, g_h2 + nxt * BH, bq,
                        attnB + (size_t)blockIdx.x * attnBS + (size_t)t * attnTS, &s);
        gsync();

        hid_phase(g_h2 + nxt * BH, W1, b1, &s);
        gsync();

        logits_phase(Wemb, bcls, outL, t, &s);
        // no barrier: next LSTM1 touches only h1/c1/emb1 (disjoint from g_hid*/outL)
    }
}

// ---------------- launch ----------------
extern "C" void kernel_launch(void* const* d_in, const int* in_sizes, int n_in,
                              void* d_out, int out_size) {
    const float* enc   = (const float*)d_in[0];
    const int*   y     = (const int*)  d_in[1];
    const float* Wemb  = (const float*)d_in[2];
    const float* Wih1  = (const float*)d_in[3];
    const float* bih1  = (const float*)d_in[4];
    const float* Whh1  = (const float*)d_in[5];
    const float* bhh1  = (const float*)d_in[6];
    const float* Wih2  = (const float*)d_in[7];
    const float* bih2  = (const float*)d_in[8];
    const float* Whh2  = (const float*)d_in[9];
    const float* bhh2  = (const float*)d_in[10];
    const float* Wq    = (const float*)d_in[11];
    const float* bq    = (const float*)d_in[12];
    const float* Wk    = (const float*)d_in[13];
    const float* bk    = (const float*)d_in[14];
    const float* Wv    = (const float*)d_in[15];
    const float* bv    = (const float*)d_in[16];
    const float* W1    = (const float*)d_in[17];
    const float* b1    = (const float*)d_in[18];
    const float* bcls  = (const float*)d_in[19];

    float* outL = (float*)d_out;
    long long need = (long long)Bc * Tc * Vc + (long long)Bc * Tc * Sc;

    float* attnB; int attnBS, attnTS;
    if ((long long)out_size >= need) {
        attnB = outL + (size_t)Bc * Tc * Vc;
        attnBS = Tc * Sc; attnTS = Sc;
    } else {
        cudaGetSymbolAddress((void**)&attnB, g_attn_dummy);
        attnBS = Sc; attnTS = 0;
    }

    decoder_kernel<<<NBLK, NTHR>>>(enc, y, Wemb, Wih1, bih1, Whh1, bhh1,
                                   Wih2, bih2, Whh2, bhh2, Wq, bq, Wk, bk,
                                   Wv, bv, W1, b1, bcls, outL, attnB, attnBS, attnTS);
}

// round 5
// speedup vs baseline: 2.2217x; 1.1358x over previous
#include <cuda_runtime.h>
#include <cuda_bf16.h>
#include <math.h>

#define Bc  64
#define Sc  512
#define Tc  256
#define Ec  512
#define Hc  512
#define KQc 256
#define Vc  1000
#define BH  (Bc*Hc)
#define NBLK 128
#define NTHR 512

typedef unsigned long long u64t;

// ---------------- device scratch ----------------
__device__ float g_k[(size_t)Bc*Sc*KQc];             // K cache fp32 [B*S, KQ]
__device__ __nv_bfloat16 g_vbf[(size_t)Bc*Sc*Ec];    // V cache bf16 [B*S, E]
__device__ float g_emb1[(size_t)Vc*4*Hc];            // token -> LSTM1 x-side gate preact (+biases)
__device__ float g_h1[2*BH], g_c1[2*BH], g_h2[2*BH], g_c2[2*BH];
__device__ float g_ctx[Bc*Ec];
__device__ float g_hidA[Bc*Hc], g_hidB[Bc*Hc];
__device__ float g_attn_dummy[Bc*Sc];

// ---------------- software grid barrier ----------------
__device__ volatile unsigned g_bar_gen;
__device__ unsigned g_bar_cnt;

__device__ __forceinline__ void gsync() {
    __syncthreads();
    if (threadIdx.x == 0) {
        unsigned gen = g_bar_gen;
        __threadfence();
        if (atomicAdd(&g_bar_cnt, 1u) == NBLK - 1) {
            g_bar_cnt = 0u;
            __threadfence();
            g_bar_gen = gen + 1u;
        } else {
            while (g_bar_gen == gen) { }
        }
        __threadfence();
    }
    __syncthreads();
}

// ---------------- f32x2 packed FMA ----------------
__device__ __forceinline__ u64t fma2(u64t a, u64t b, u64t c) {
    u64t d;
    asm("fma.rn.f32x2 %0, %1, %2, %3;" : "=l"(d) : "l"(a), "l"(b), "l"(c));
    return d;
}
__device__ __forceinline__ float hsum2(u64t v) {
    return __uint_as_float((unsigned)v) + __uint_as_float((unsigned)(v >> 32));
}

// ---------------- shared memory ----------------
struct __align__(16) Smem {
    union {
        struct { float As[16][68]; float Ws[16][68]; } gm;                     // precompute
        struct { float As[64][68]; float Ws[16][68]; float red[16][68]; } ph;  // step GEMMs
        struct { float qh[512]; float qs[256]; float sc[512]; float ctxp[512];
                 float red[16]; float red2[16]; } at;                          // attention
    } u;
};

// ---------------- staging ----------------
__device__ __forceinline__ void stageA(const float* __restrict__ A, int ldA, int kb, Smem* s) {
    int t = threadIdx.x;
    #pragma unroll
    for (int u2 = 0; u2 < 2; u2++) {
        int idx = t + u2 * NTHR;                 // 1024 float4 units = 64 rows x 16
        int row = idx >> 4, c4 = idx & 15;
        *(float4*)&s->u.ph.As[row][c4 * 4] =
            *(const float4*)&A[(size_t)row * ldA + kb + c4 * 4];
    }
}

template<int TN, int LSTMMAP>
__device__ __forceinline__ void stageW(const float* __restrict__ W, int ldW, int kb, int tile,
                                       Smem* s) {
    int t = threadIdx.x;
    if (t < TN * 16) {
        int r = t >> 4, c4 = t & 15;
        int row = LSTMMAP ? ((r >> 2) * Hc + tile * 4 + (r & 3)) : (tile * TN + r);
        *(float4*)&s->u.ph.Ws[r][c4 * 4] =
            *(const float4*)&W[(size_t)row * ldW + kb + c4 * 4];
    }
}

// ---------------- micro-kernels ----------------
// TN=16 (LSTM): thread -> col r = tid%16, b-pair b0 = (tid/16)*2; acc[4] = 2 outs x 2 chains
__device__ __forceinline__ void mm16(u64t* acc, Smem* s) {
    int t = threadIdx.x;
    int r = t & 15, b0 = (t >> 4) * 2;
    #pragma unroll
    for (int kk = 0; kk < 64; kk += 4) {
        ulonglong2 w  = *(const ulonglong2*)&s->u.ph.Ws[r][kk];
        ulonglong2 a0 = *(const ulonglong2*)&s->u.ph.As[b0][kk];
        ulonglong2 a1 = *(const ulonglong2*)&s->u.ph.As[b0 + 1][kk];
        acc[0] = fma2(a0.x, w.x, acc[0]);
        acc[1] = fma2(a0.y, w.y, acc[1]);
        acc[2] = fma2(a1.x, w.x, acc[2]);
        acc[3] = fma2(a1.y, w.y, acc[3]);
    }
}

// TN=8 (hidA / logits): thread -> col r = tid%8, b = tid/8; acc[2] chains
__device__ __forceinline__ void mm8(u64t* acc, Smem* s) {
    int t = threadIdx.x;
    int r = t & 7, b = t >> 3;
    #pragma unroll
    for (int kk = 0; kk < 64; kk += 4) {
        ulonglong2 w = *(const ulonglong2*)&s->u.ph.Ws[r][kk];
        ulonglong2 a = *(const ulonglong2*)&s->u.ph.As[b][kk];
        acc[0] = fma2(a.x, w.x, acc[0]);
        acc[1] = fma2(a.y, w.y, acc[1]);
    }
}

// TN=4 (hidB): only tid<256 compute; col r = tid%4, b = tid/4
__device__ __forceinline__ void mm4(u64t* acc, Smem* s) {
    int t = threadIdx.x;
    if (t < 256) {
        int r = t & 3, b = t >> 2;
        #pragma unroll
        for (int kk = 0; kk < 64; kk += 4) {
            ulonglong2 w = *(const ulonglong2*)&s->u.ph.Ws[r][kk];
            ulonglong2 a = *(const ulonglong2*)&s->u.ph.As[b][kk];
            acc[0] = fma2(a.x, w.x, acc[0]);
            acc[1] = fma2(a.y, w.y, acc[1]);
        }
    }
}

// ---------------- LSTM phase ----------------
template<bool HASX>
__device__ void lstm_phase(const float* __restrict__ hin, const float* __restrict__ cin,
                           float* __restrict__ hout, float* __restrict__ cout,
                           const float* __restrict__ xsrc, const int* __restrict__ y, int t,
                           const float* __restrict__ Wih, const float* __restrict__ Whh,
                           const float* __restrict__ bih, const float* __restrict__ bhh,
                           Smem* s) {
    int tile = blockIdx.x;                       // j-quad: j = tile*4 + jj
    u64t acc[4] = {0ull, 0ull, 0ull, 0ull};
    for (int kb = 0; kb < Hc; kb += 64) {
        __syncthreads();
        stageA(hin, Hc, kb, s);
        stageW<16, 1>(Whh, Hc, kb, tile, s);
        __syncthreads();
        mm16(acc, s);
    }
    if (HASX) {
        for (int kb = 0; kb < Hc; kb += 64) {
            __syncthreads();
            stageA(xsrc, Hc, kb, s);
            stageW<16, 1>(Wih, Hc, kb, tile, s);
            __syncthreads();
            mm16(acc, s);
        }
    }
    __syncthreads();
    {
        int t0 = threadIdx.x;
        int r = t0 & 15, b0 = (t0 >> 4) * 2;
        s->u.ph.red[r][b0]     = hsum2(acc[0]) + hsum2(acc[1]);
        s->u.ph.red[r][b0 + 1] = hsum2(acc[2]) + hsum2(acc[3]);
    }
    __syncthreads();
    int u = threadIdx.x;
    if (u < 256) {
        int jj = u & 3, b = u >> 2;
        int j = tile * 4 + jj;
        float pi = s->u.ph.red[0 * 4 + jj][b];
        float pf = s->u.ph.red[1 * 4 + jj][b];
        float pg = s->u.ph.red[2 * 4 + jj][b];
        float po = s->u.ph.red[3 * 4 + jj][b];
        if (!HASX) {
            int tok = (t == 0) ? 0 : y[b * Tc + t - 1];
            const float* e = g_emb1 + (size_t)tok * (4 * Hc);
            pi += e[j]; pf += e[Hc + j]; pg += e[2 * Hc + j]; po += e[3 * Hc + j];
        } else {
            pi += bih[j]          + bhh[j];
            pf += bih[Hc + j]     + bhh[Hc + j];
            pg += bih[2 * Hc + j] + bhh[2 * Hc + j];
            po += bih[3 * Hc + j] + bhh[3 * Hc + j];
        }
        float si = 1.f / (1.f + __expf(-pi));
        float sf = 1.f / (1.f + __expf(-pf));
        float so = 1.f / (1.f + __expf(-po));
        float cN = sf * cin[b * Hc + j] + si * tanhf(pg);
        float hN = so * tanhf(cN);
        hout[b * Hc + j] = hN;
        cout[b * Hc + j] = cN;
    }
}

// ---------------- q + scores + softmax + attn-out + ctx partials (blocks 0..63) ----------------
__device__ void qattn_phase(int b, const float* __restrict__ h2n,
                            const float* __restrict__ Wq, const float* __restrict__ bq,
                            float* __restrict__ attn_out, Smem* s) {
    int tid = threadIdx.x, warp = tid >> 5, lane = tid & 31;

    if (tid < Hc) s->u.at.qh[tid] = h2n[b * Hc + tid];
    __syncthreads();

    float hr[16];
    #pragma unroll
    for (int u2 = 0; u2 < 16; u2++) hr[u2] = s->u.at.qh[lane * 16 + u2];

    // q[j] = h2[b] . Wq[j] + bq[j]   (fp32)
    for (int j = warp; j < KQc; j += 16) {
        const float* wr = Wq + (size_t)j * Hc + lane * 16;
        float sum = 0.f;
        #pragma unroll
        for (int q4 = 0; q4 < 4; q4++) {
            float4 w = *(const float4*)(wr + q4 * 4);
            sum += hr[q4 * 4] * w.x + hr[q4 * 4 + 1] * w.y
                 + hr[q4 * 4 + 2] * w.z + hr[q4 * 4 + 3] * w.w;
        }
        #pragma unroll
        for (int o = 16; o; o >>= 1) sum += __shfl_down_sync(~0u, sum, o);
        if (lane == 0) s->u.at.qs[j] = sum + bq[j];
    }
    __syncthreads();

    float qr[8];
    #pragma unroll
    for (int u2 = 0; u2 < 8; u2++) qr[u2] = s->u.at.qs[lane * 8 + u2];

    // scores (fp32 K)
    for (int ss = warp; ss < Sc; ss += 16) {
        const float* kr = g_k + ((size_t)b * Sc + ss) * KQc + lane * 8;
        float4 k0 = *(const float4*)kr;
        float4 k1 = *(const float4*)(kr + 4);
        float sum = qr[0]*k0.x + qr[1]*k0.y + qr[2]*k0.z + qr[3]*k0.w
                  + qr[4]*k1.x + qr[5]*k1.y + qr[6]*k1.z + qr[7]*k1.w;
        #pragma unroll
        for (int o = 16; o; o >>= 1) sum += __shfl_down_sync(~0u, sum, o);
        if (lane == 0) s->u.at.sc[ss] = sum * 0.0625f;      // 1/sqrt(256)
    }
    __syncthreads();

    // softmax over 512 (one value per thread)
    float v = s->u.at.sc[tid];
    float m = v;
    #pragma unroll
    for (int o = 16; o; o >>= 1) m = fmaxf(m, __shfl_xor_sync(~0u, m, o));
    if (lane == 0) s->u.at.red[warp] = m;
    __syncthreads();
    float mm = s->u.at.red[0];
    #pragma unroll
    for (int w = 1; w < 16; w++) mm = fmaxf(mm, s->u.at.red[w]);
    float e = __expf(v - mm);
    float ssum = e;
    #pragma unroll
    for (int o = 16; o; o >>= 1) ssum += __shfl_xor_sync(~0u, ssum, o);
    if (lane == 0) s->u.at.red2[warp] = ssum;
    __syncthreads();
    float Z = 0.f;
    #pragma unroll
    for (int w = 0; w < 16; w++) Z += s->u.at.red2[w];
    float p = e / Z;
    s->u.at.sc[tid] = p;
    attn_out[tid] = p;
    __syncthreads();

    // ctx[b,e] = sum_s p[s] * V[b,s,e]  (bf16 V); 2-way s-split, e-pair per thread
    int half = tid >> 8;
    int i2 = tid & 255;
    int e2 = i2 * 2;
    const __nv_bfloat16* vb = g_vbf + (size_t)b * Sc * Ec + e2;
    float ax = 0.f, ay = 0.f;
    int s0 = half * 256;
    #pragma unroll 8
    for (int ss2 = 0; ss2 < 256; ss2++) {
        float pp = s->u.at.sc[s0 + ss2];
        float2 vv = __bfloat1622float2(*(const __nv_bfloat162*)(vb + (size_t)(s0 + ss2) * Ec));
        ax += pp * vv.x; ay += pp * vv.y;
    }
    if (half == 1) {
        s->u.at.ctxp[e2]     = ax;
        s->u.at.ctxp[e2 + 1] = ay;
    }
    __syncthreads();
    if (half == 0) {
        g_ctx[b * Ec + e2]     = ax + s->u.at.ctxp[e2];
        g_ctx[b * Ec + e2 + 1] = ay + s->u.at.ctxp[e2 + 1];
    }
}

// ---------------- hidA = h2 @ W1[:, :512] + b1 (blocks 64..127; TN=8, 64 tiles) ----------------
__device__ void hidA_phase(const float* __restrict__ h2n, const float* __restrict__ W1,
                           const float* __restrict__ b1, Smem* s) {
    int tile = blockIdx.x - 64;
    u64t acc[2] = {0ull, 0ull};
    for (int kb = 0; kb < Hc; kb += 64) {
        __syncthreads();
        stageA(h2n, Hc, kb, s);
        stageW<8, 0>(W1, Hc + Ec, kb, tile, s);
        __syncthreads();
        mm8(acc, s);
    }
    int t0 = threadIdx.x;
    int r = t0 & 7, b = t0 >> 3;
    int j = tile * 8 + r;
    g_hidA[(size_t)b * Hc + j] = hsum2(acc[0]) + hsum2(acc[1]) + b1[j];
}

// ---------------- hidB = ctx @ W1[:, 512:] (all blocks; TN=4, 128 tiles) ----------------
__device__ void hidB_phase(const float* __restrict__ W1, Smem* s) {
    int tile = blockIdx.x;
    u64t acc[2] = {0ull, 0ull};
    for (int kb = 0; kb < Ec; kb += 64) {
        __syncthreads();
        stageA(g_ctx, Ec, kb, s);
        stageW<4, 0>(W1 + Ec, Hc + Ec, kb, tile, s);
        __syncthreads();
        mm4(acc, s);
    }
    int t0 = threadIdx.x;
    if (t0 < 256) {
        int r = t0 & 3, b = t0 >> 2;
        int j = tile * 4 + r;
        g_hidB[(size_t)b * Hc + j] = hsum2(acc[0]) + hsum2(acc[1]);
    }
}

// ---------------- logits = relu(hidA+hidB) @ W_emb^T + b_cls (TN=8, 125 tiles) ----------------
__device__ void logits_phase(const float* __restrict__ Wemb, const float* __restrict__ bcls,
                             float* __restrict__ outL, int t, Smem* s) {
    int tile = blockIdx.x;
    if (tile >= Vc / 8) return;
    u64t acc[2] = {0ull, 0ull};
    for (int kb = 0; kb < Hc; kb += 64) {
        __syncthreads();
        {
            int tt = threadIdx.x;
            #pragma unroll
            for (int u2 = 0; u2 < 2; u2++) {
                int idx = tt + u2 * NTHR;
                int row = idx >> 4, c4 = idx & 15;
                float4 a  = *(const float4*)&g_hidA[(size_t)row * Hc + kb + c4 * 4];
                float4 bb = *(const float4*)&g_hidB[(size_t)row * Hc + kb + c4 * 4];
                float4 vv;
                vv.x = fmaxf(a.x + bb.x, 0.f);
                vv.y = fmaxf(a.y + bb.y, 0.f);
                vv.z = fmaxf(a.z + bb.z, 0.f);
                vv.w = fmaxf(a.w + bb.w, 0.f);
                *(float4*)&s->u.ph.As[row][c4 * 4] = vv;
            }
            stageW<8, 0>(Wemb, Hc, kb, tile, s);
        }
        __syncthreads();
        mm8(acc, s);
    }
    int t0 = threadIdx.x;
    int r = t0 & 7, b = t0 >> 3;
    int j = tile * 8 + r;
    outL[((size_t)b * Tc + t) * Vc + j] = hsum2(acc[0]) + hsum2(acc[1]) + bcls[j];
}

// ---------------- precompute 64x64 GEMM tile ----------------
__device__ __forceinline__ void storeC(float* C, size_t idx, float v) { C[idx] = v; }
__device__ __forceinline__ void storeC(__nv_bfloat16* C, size_t idx, float v) {
    C[idx] = __float2bfloat16(v);
}

template<class OUT>
__device__ void gemm_tile(const float* __restrict__ A, const float* __restrict__ W,
                          const float* __restrict__ b1, const float* __restrict__ b2,
                          OUT* __restrict__ C, int M, int N, int K, int m0, int n0, Smem* s) {
    int tid = threadIdx.x;
    int tx = tid & 15, ty = tid >> 4;            // ty in [0,32): row-pair
    float acc[2][4] = {};
    for (int kb = 0; kb < K; kb += 16) {
        __syncthreads();
        #pragma unroll
        for (int u2 = 0; u2 < 2; u2++) {
            int i = tid + u2 * NTHR;             // 1024 scalars... 64 rows x 16 k
            int r = i >> 4, kk = i & 15;
            int ra = m0 + r; if (ra >= M) ra = M - 1;
            s->u.gm.As[kk][r] = A[(size_t)ra * K + kb + kk];
            s->u.gm.Ws[kk][r] = W[(size_t)(n0 + r) * K + kb + kk];
        }
        __syncthreads();
        #pragma unroll
        for (int kk = 0; kk < 16; kk++) {
            float a0 = s->u.gm.As[kk][ty * 2];
            float a1 = s->u.gm.As[kk][ty * 2 + 1];
            float4 w4 = *(const float4*)&s->u.gm.Ws[kk][tx * 4];
            float wr[4] = {w4.x, w4.y, w4.z, w4.w};
            #pragma unroll
            for (int j = 0; j < 4; j++) {
                acc[0][j] += a0 * wr[j];
                acc[1][j] += a1 * wr[j];
            }
        }
    }
    __syncthreads();
    #pragma unroll
    for (int i = 0; i < 2; i++) {
        int row = m0 + ty * 2 + i;
        if (row < M) {
            #pragma unroll
            for (int j = 0; j < 4; j++) {
                int col = n0 + tx * 4 + j;
                float v = acc[i][j] + b1[col];
                if (b2) v += b2[col];
                storeC(C, (size_t)row * N + col, v);
            }
        }
    }
}

// ---------------- persistent kernel ----------------
__global__ void __launch_bounds__(NTHR, 1)
decoder_kernel(const float* __restrict__ enc, const int* __restrict__ y,
               const float* __restrict__ Wemb,
               const float* __restrict__ Wih1, const float* __restrict__ bih1,
               const float* __restrict__ Whh1, const float* __restrict__ bhh1,
               const float* __restrict__ Wih2, const float* __restrict__ bih2,
               const float* __restrict__ Whh2, const float* __restrict__ bhh2,
               const float* __restrict__ Wq,  const float* __restrict__ bq,
               const float* __restrict__ Wk,  const float* __restrict__ bk,
               const float* __restrict__ Wv,  const float* __restrict__ bv,
               const float* __restrict__ W1,  const float* __restrict__ b1,
               const float* __restrict__ bcls,
               float* __restrict__ outL, float* __restrict__ attnB,
               int attnBS, int attnTS)
{
    __shared__ Smem s;
    int tid = threadIdx.x;

    for (int i = blockIdx.x * NTHR + tid; i < BH; i += NBLK * NTHR) {
        g_h1[i] = 0.f; g_c1[i] = 0.f; g_h2[i] = 0.f; g_c2[i] = 0.f;
    }
    gsync();

    // precompute: K (fp32), V (bf16), LSTM1 x-side token table (fp32)
    {
        const int nKt = (Bc * Sc / 64) * (KQc / 64);   // 2048
        const int nVt = (Bc * Sc / 64) * (Ec / 64);    // 4096
        const int nEt = 16 * (4 * Hc / 64);            // 512
        for (int idx = blockIdx.x; idx < nKt + nVt + nEt; idx += NBLK) {
            if (idx < nKt) {
                int m0 = (idx / (KQc / 64)) * 64, n0 = (idx % (KQc / 64)) * 64;
                gemm_tile(enc, Wk, bk, (const float*)0, g_k, Bc * Sc, KQc, Ec, m0, n0, &s);
            } else if (idx < nKt + nVt) {
                int i2 = idx - nKt;
                int m0 = (i2 / (Ec / 64)) * 64, n0 = (i2 % (Ec / 64)) * 64;
                gemm_tile(enc, Wv, bv, (const float*)0, g_vbf, Bc * Sc, Ec, Ec, m0, n0, &s);
            } else {
                int i2 = idx - nKt - nVt;
                int m0 = (i2 / 32) * 64, n0 = (i2 % 32) * 64;
                gemm_tile(Wemb, Wih1, bih1, bhh1, g_emb1, Vc, 4 * Hc, Hc, m0, n0, &s);
            }
        }
    }
    gsync();

    for (int t = 0; t < Tc; t++) {
        int cur = t & 1, nxt = cur ^ 1;

        // P1: LSTM1 (h-side GEMM; x-side from token table)
        lstm_phase<false>(g_h1 + cur * BH, g_c1 + cur * BH,
                          g_h1 + nxt * BH, g_c1 + nxt * BH,
                          (const float*)0, y, t, (const float*)0, Whh1,
                          (const float*)0, (const float*)0, &s);
        gsync();

        // P2: LSTM2 (h-side + x-side = new h1)
        lstm_phase<true>(g_h2 + cur * BH, g_c2 + cur * BH,
                         g_h2 + nxt * BH, g_c2 + nxt * BH,
                         g_h1 + nxt * BH, y, t, Wih2, Whh2, bih2, bhh2, &s);
        gsync();

        // P3: qattn (blocks 0..63) || hidA (blocks 64..127)
        if (blockIdx.x < Bc)
            qattn_phase(blockIdx.x, g_h2 + nxt * BH, Wq, bq,
                        attnB + (size_t)blockIdx.x * attnBS + (size_t)t * attnTS, &s);
        else
            hidA_phase(g_h2 + nxt * BH, W1, b1, &s);
        gsync();

        // P4: hidB (ctx part)
        hidB_phase(W1, &s);
        gsync();

        // P5: logits (no trailing barrier: next P1 touches disjoint state;
        //     P2(t+1) starts only after the P1(t+1) barrier, which implies all
        //     blocks have finished P5(t))
        logits_phase(Wemb, bcls, outL, t, &s);
    }
}

// ---------------- launch ----------------
extern "C" void kernel_launch(void* const* d_in, const int* in_sizes, int n_in,
                              void* d_out, int out_size) {
    const float* enc   = (const float*)d_in[0];
    const int*   y     = (const int*)  d_in[1];
    const float* Wemb  = (const float*)d_in[2];
    const float* Wih1  = (const float*)d_in[3];
    const float* bih1  = (const float*)d_in[4];
    const float* Whh1  = (const float*)d_in[5];
    const float* bhh1  = (const float*)d_in[6];
    const float* Wih2  = (const float*)d_in[7];
    const float* bih2  = (const float*)d_in[8];
    const float* Whh2  = (const float*)d_in[9];
    const float* bhh2  = (const float*)d_in[10];
    const float* Wq    = (const float*)d_in[11];
    const float* bq    = (const float*)d_in[12];
    const float* Wk    = (const float*)d_in[13];
    const float* bk    = (const float*)d_in[14];
    const float* Wv    = (const float*)d_in[15];
    const float* bv    = (const float*)d_in[16];
    const float* W1    = (const float*)d_in[17];
    const float* b1    = (const float*)d_in[18];
    const float* bcls  = (const float*)d_in[19];

    float* outL = (float*)d_out;
    long long need = (long long)Bc * Tc * Vc + (long long)Bc * Tc * Sc;

    float* attnB; int attnBS, attnTS;
    if ((long long)out_size >= need) {
        attnB = outL + (size_t)Bc * Tc * Vc;
        attnBS = Tc * Sc; attnTS = Sc;
    } else {
        cudaGetSymbolAddress((void**)&attnB, g_attn_dummy);
        attnBS = Sc; attnTS = 0;
    }

    decoder_kernel<<<NBLK, NTHR>>>(enc, y, Wemb, Wih1, bih1, Whh1, bhh1,
                                   Wih2, bih2, Whh2, bhh2, Wq, bq, Wk, bk,
                                   Wv, bv, W1, b1, bcls, outL, attnB, attnBS, attnTS);
}

// round 6
// speedup vs baseline: 2.4448x; 1.1004x over previous
#include <cuda_runtime.h>
#include <cuda_bf16.h>
#include <math.h>

#define Bc  64
#define Sc  512
#define Tc  256
#define Ec  512
#define Hc  512
#define KQc 256
#define Vc  1000
#define BH  (Bc*Hc)
#define NBLK 128
#define NTHR 512

typedef unsigned long long u64t;

// ---------------- device scratch ----------------
__device__ float g_k[(size_t)Bc*Sc*KQc];             // K cache fp32 [B*S, KQ]
__device__ __nv_bfloat16 g_vbf[(size_t)Bc*Sc*Ec];    // V cache bf16 [B*S, E]
__device__ float g_emb1[(size_t)Vc*4*Hc];            // token -> LSTM1 x-side gate preact (+biases)
__device__ float g_h1[2*BH], g_c1[2*BH], g_h2[2*BH], g_c2[2*BH];
__device__ float g_ctx[Bc*Ec];
__device__ float g_hidA[Bc*Hc], g_hidB[Bc*Hc];
__device__ float g_attn_dummy[Bc*Sc];

// ---------------- software grid barrier ----------------
__device__ volatile unsigned g_bar_gen;
__device__ unsigned g_bar_cnt;

__device__ __forceinline__ void gsync() {
    __syncthreads();
    if (threadIdx.x == 0) {
        unsigned gen = g_bar_gen;
        __threadfence();
        if (atomicAdd(&g_bar_cnt, 1u) == NBLK - 1) {
            g_bar_cnt = 0u;
            __threadfence();
            g_bar_gen = gen + 1u;
        } else {
            while (g_bar_gen == gen) { }
        }
        __threadfence();
    }
    __syncthreads();
}

// ---------------- f32x2 packed FMA ----------------
__device__ __forceinline__ u64t fma2(u64t a, u64t b, u64t c) {
    u64t d;
    asm("fma.rn.f32x2 %0, %1, %2, %3;" : "=l"(d) : "l"(a), "l"(b), "l"(c));
    return d;
}
__device__ __forceinline__ float hsum2(u64t v) {
    return __uint_as_float((unsigned)v) + __uint_as_float((unsigned)(v >> 32));
}

// ---------------- shared memory ----------------
struct __align__(16) Smem {
    union {
        struct { float As[16][68]; float Ws[16][68]; } gm;                     // precompute
        struct { float As[64][68]; float Ws[16][68]; float red[16][68]; } ph;  // step GEMMs
        struct { float qh[512]; float qs[256]; float sc[512]; float ctxp[512];
                 float red[16]; float red2[16]; } at;                          // attention
    } u;
};

// ---------------- staging ----------------
__device__ __forceinline__ void stageA(const float* __restrict__ A, int ldA, int kb, Smem* s) {
    int t = threadIdx.x;
    #pragma unroll
    for (int u2 = 0; u2 < 2; u2++) {
        int idx = t + u2 * NTHR;                 // 1024 float4 units = 64 rows x 16
        int row = idx >> 4, c4 = idx & 15;
        *(float4*)&s->u.ph.As[row][c4 * 4] =
            *(const float4*)&A[(size_t)row * ldA + kb + c4 * 4];
    }
}

template<int TN, int LSTMMAP>
__device__ __forceinline__ void stageW(const float* __restrict__ W, int ldW, int kb, int tile,
                                       Smem* s) {
    int t = threadIdx.x;
    if (t < TN * 16) {
        int r = t >> 4, c4 = t & 15;
        int row = LSTMMAP ? ((r >> 2) * Hc + tile * 4 + (r & 3)) : (tile * TN + r);
        *(float4*)&s->u.ph.Ws[r][c4 * 4] =
            *(const float4*)&W[(size_t)row * ldW + kb + c4 * 4];
    }
}

// ---------------- micro-kernels ----------------
// TN=16 (LSTM): thread -> col r = tid%16, b-pair b0 = (tid/16)*2; acc[4] = 2 outs x 2 chains
__device__ __forceinline__ void mm16(u64t* acc, Smem* s) {
    int t = threadIdx.x;
    int r = t & 15, b0 = (t >> 4) * 2;
    #pragma unroll
    for (int kk = 0; kk < 64; kk += 4) {
        ulonglong2 w  = *(const ulonglong2*)&s->u.ph.Ws[r][kk];
        ulonglong2 a0 = *(const ulonglong2*)&s->u.ph.As[b0][kk];
        ulonglong2 a1 = *(const ulonglong2*)&s->u.ph.As[b0 + 1][kk];
        acc[0] = fma2(a0.x, w.x, acc[0]);
        acc[1] = fma2(a0.y, w.y, acc[1]);
        acc[2] = fma2(a1.x, w.x, acc[2]);
        acc[3] = fma2(a1.y, w.y, acc[3]);
    }
}

// TN=8 (hidA / logits): thread -> col r = tid%8, b = tid/8; acc[2] chains
__device__ __forceinline__ void mm8(u64t* acc, Smem* s) {
    int t = threadIdx.x;
    int r = t & 7, b = t >> 3;
    #pragma unroll
    for (int kk = 0; kk < 64; kk += 4) {
        ulonglong2 w = *(const ulonglong2*)&s->u.ph.Ws[r][kk];
        ulonglong2 a = *(const ulonglong2*)&s->u.ph.As[b][kk];
        acc[0] = fma2(a.x, w.x, acc[0]);
        acc[1] = fma2(a.y, w.y, acc[1]);
    }
}

// TN=4 (hidB): only tid<256 compute; col r = tid%4, b = tid/4
__device__ __forceinline__ void mm4(u64t* acc, Smem* s) {
    int t = threadIdx.x;
    if (t < 256) {
        int r = t & 3, b = t >> 2;
        #pragma unroll
        for (int kk = 0; kk < 64; kk += 4) {
            ulonglong2 w = *(const ulonglong2*)&s->u.ph.Ws[r][kk];
            ulonglong2 a = *(const ulonglong2*)&s->u.ph.As[b][kk];
            acc[0] = fma2(a.x, w.x, acc[0]);
            acc[1] = fma2(a.y, w.y, acc[1]);
        }
    }
}

// ---------------- LSTM phase ----------------
template<bool HASX>
__device__ void lstm_phase(const float* __restrict__ hin, const float* __restrict__ cin,
                           float* __restrict__ hout, float* __restrict__ cout,
                           const float* __restrict__ xsrc, const int* __restrict__ y, int t,
                           const float* __restrict__ Wih, const float* __restrict__ Whh,
                           const float* __restrict__ bih, const float* __restrict__ bhh,
                           Smem* s) {
    int tile = blockIdx.x;                       // j-quad: j = tile*4 + jj
    u64t acc[4] = {0ull, 0ull, 0ull, 0ull};
    for (int kb = 0; kb < Hc; kb += 64) {
        __syncthreads();
        stageA(hin, Hc, kb, s);
        stageW<16, 1>(Whh, Hc, kb, tile, s);
        __syncthreads();
        mm16(acc, s);
    }
    if (HASX) {
        for (int kb = 0; kb < Hc; kb += 64) {
            __syncthreads();
            stageA(xsrc, Hc, kb, s);
            stageW<16, 1>(Wih, Hc, kb, tile, s);
            __syncthreads();
            mm16(acc, s);
        }
    }
    __syncthreads();
    {
        int t0 = threadIdx.x;
        int r = t0 & 15, b0 = (t0 >> 4) * 2;
        s->u.ph.red[r][b0]     = hsum2(acc[0]) + hsum2(acc[1]);
        s->u.ph.red[r][b0 + 1] = hsum2(acc[2]) + hsum2(acc[3]);
    }
    __syncthreads();
    int u = threadIdx.x;
    if (u < 256) {
        int jj = u & 3, b = u >> 2;
        int j = tile * 4 + jj;
        float pi = s->u.ph.red[0 * 4 + jj][b];
        float pf = s->u.ph.red[1 * 4 + jj][b];
        float pg = s->u.ph.red[2 * 4 + jj][b];
        float po = s->u.ph.red[3 * 4 + jj][b];
        if (!HASX) {
            int tok = (t == 0) ? 0 : y[b * Tc + t - 1];
            const float* e = g_emb1 + (size_t)tok * (4 * Hc);
            pi += e[j]; pf += e[Hc + j]; pg += e[2 * Hc + j]; po += e[3 * Hc + j];
        } else {
            pi += bih[j]          + bhh[j];
            pf += bih[Hc + j]     + bhh[Hc + j];
            pg += bih[2 * Hc + j] + bhh[2 * Hc + j];
            po += bih[3 * Hc + j] + bhh[3 * Hc + j];
        }
        float si = 1.f / (1.f + __expf(-pi));
        float sf = 1.f / (1.f + __expf(-pf));
        float so = 1.f / (1.f + __expf(-po));
        float cN = sf * cin[b * Hc + j] + si * tanhf(pg);
        float hN = so * tanhf(cN);
        hout[b * Hc + j] = hN;
        cout[b * Hc + j] = cN;
    }
}

// ---------------- q + scores + softmax + attn-out + ctx partials (blocks 0..63) ----------------
__device__ void qattn_phase(int b, const float* __restrict__ h2n,
                            const float* __restrict__ Wq, const float* __restrict__ bq,
                            float* __restrict__ attn_out, Smem* s) {
    int tid = threadIdx.x, warp = tid >> 5, lane = tid & 31;

    if (tid < Hc) s->u.at.qh[tid] = h2n[b * Hc + tid];
    __syncthreads();

    float hr[16];
    #pragma unroll
    for (int u2 = 0; u2 < 16; u2++) hr[u2] = s->u.at.qh[lane * 16 + u2];

    // q[j] = h2[b] . Wq[j] + bq[j]   (fp32)
    for (int j = warp; j < KQc; j += 16) {
        const float* wr = Wq + (size_t)j * Hc + lane * 16;
        float sum = 0.f;
        #pragma unroll
        for (int q4 = 0; q4 < 4; q4++) {
            float4 w = *(const float4*)(wr + q4 * 4);
            sum += hr[q4 * 4] * w.x + hr[q4 * 4 + 1] * w.y
                 + hr[q4 * 4 + 2] * w.z + hr[q4 * 4 + 3] * w.w;
        }
        #pragma unroll
        for (int o = 16; o; o >>= 1) sum += __shfl_down_sync(~0u, sum, o);
        if (lane == 0) s->u.at.qs[j] = sum + bq[j];
    }
    __syncthreads();

    float qr[8];
    #pragma unroll
    for (int u2 = 0; u2 < 8; u2++) qr[u2] = s->u.at.qs[lane * 8 + u2];

    // scores (fp32 K)
    for (int ss = warp; ss < Sc; ss += 16) {
        const float* kr = g_k + ((size_t)b * Sc + ss) * KQc + lane * 8;
        float4 k0 = *(const float4*)kr;
        float4 k1 = *(const float4*)(kr + 4);
        float sum = qr[0]*k0.x + qr[1]*k0.y + qr[2]*k0.z + qr[3]*k0.w
                  + qr[4]*k1.x + qr[5]*k1.y + qr[6]*k1.z + qr[7]*k1.w;
        #pragma unroll
        for (int o = 16; o; o >>= 1) sum += __shfl_down_sync(~0u, sum, o);
        if (lane == 0) s->u.at.sc[ss] = sum * 0.0625f;      // 1/sqrt(256)
    }
    __syncthreads();

    // softmax over 512 (one value per thread)
    float v = s->u.at.sc[tid];
    float m = v;
    #pragma unroll
    for (int o = 16; o; o >>= 1) m = fmaxf(m, __shfl_xor_sync(~0u, m, o));
    if (lane == 0) s->u.at.red[warp] = m;
    __syncthreads();
    float mm = s->u.at.red[0];
    #pragma unroll
    for (int w = 1; w < 16; w++) mm = fmaxf(mm, s->u.at.red[w]);
    float e = __expf(v - mm);
    float ssum = e;
    #pragma unroll
    for (int o = 16; o; o >>= 1) ssum += __shfl_xor_sync(~0u, ssum, o);
    if (lane == 0) s->u.at.red2[warp] = ssum;
    __syncthreads();
    float Z = 0.f;
    #pragma unroll
    for (int w = 0; w < 16; w++) Z += s->u.at.red2[w];
    float p = e / Z;
    s->u.at.sc[tid] = p;
    attn_out[tid] = p;
    __syncthreads();

    // ctx[b,e] = sum_s p[s] * V[b,s,e]  (bf16 V); 2-way s-split, e-pair per thread
    int half = tid >> 8;
    int i2 = tid & 255;
    int e2 = i2 * 2;
    const __nv_bfloat16* vb = g_vbf + (size_t)b * Sc * Ec + e2;
    float ax = 0.f, ay = 0.f;
    int s0 = half * 256;
    #pragma unroll 8
    for (int ss2 = 0; ss2 < 256; ss2++) {
        float pp = s->u.at.sc[s0 + ss2];
        float2 vv = __bfloat1622float2(*(const __nv_bfloat162*)(vb + (size_t)(s0 + ss2) * Ec));
        ax += pp * vv.x; ay += pp * vv.y;
    }
    if (half == 1) {
        s->u.at.ctxp[e2]     = ax;
        s->u.at.ctxp[e2 + 1] = ay;
    }
    __syncthreads();
    if (half == 0) {
        g_ctx[b * Ec + e2]     = ax + s->u.at.ctxp[e2];
        g_ctx[b * Ec + e2 + 1] = ay + s->u.at.ctxp[e2 + 1];
    }
}

// ---------------- hidA = h2 @ W1[:, :512] + b1 (blocks 64..127; TN=8, 64 tiles) ----------------
__device__ void hidA_phase(const float* __restrict__ h2n, const float* __restrict__ W1,
                           const float* __restrict__ b1, Smem* s) {
    int tile = blockIdx.x - 64;
    u64t acc[2] = {0ull, 0ull};
    for (int kb = 0; kb < Hc; kb += 64) {
        __syncthreads();
        stageA(h2n, Hc, kb, s);
        stageW<8, 0>(W1, Hc + Ec, kb, tile, s);
        __syncthreads();
        mm8(acc, s);
    }
    int t0 = threadIdx.x;
    int r = t0 & 7, b = t0 >> 3;
    int j = tile * 8 + r;
    g_hidA[(size_t)b * Hc + j] = hsum2(acc[0]) + hsum2(acc[1]) + b1[j];
}

// ---------------- hidB = ctx @ W1[:, 512:] (all blocks; TN=4, 128 tiles) ----------------
__device__ void hidB_phase(const float* __restrict__ W1, Smem* s) {
    int tile = blockIdx.x;
    u64t acc[2] = {0ull, 0ull};
    for (int kb = 0; kb < Ec; kb += 64) {
        __syncthreads();
        stageA(g_ctx, Ec, kb, s);
        stageW<4, 0>(W1 + Ec, Hc + Ec, kb, tile, s);
        __syncthreads();
        mm4(acc, s);
    }
    int t0 = threadIdx.x;
    if (t0 < 256) {
        int r = t0 & 3, b = t0 >> 2;
        int j = tile * 4 + r;
        g_hidB[(size_t)b * Hc + j] = hsum2(acc[0]) + hsum2(acc[1]);
    }
}

// ---------------- logits = relu(hidA+hidB) @ W_emb^T + b_cls (TN=8, 125 tiles) ----------------
__device__ void logits_phase(const float* __restrict__ Wemb, const float* __restrict__ bcls,
                             float* __restrict__ outL, int t, Smem* s) {
    int tile = blockIdx.x;
    if (tile >= Vc / 8) return;
    u64t acc[2] = {0ull, 0ull};
    for (int kb = 0; kb < Hc; kb += 64) {
        __syncthreads();
        {
            int tt = threadIdx.x;
            #pragma unroll
            for (int u2 = 0; u2 < 2; u2++) {
                int idx = tt + u2 * NTHR;
                int row = idx >> 4, c4 = idx & 15;
                float4 a  = *(const float4*)&g_hidA[(size_t)row * Hc + kb + c4 * 4];
                float4 bb = *(const float4*)&g_hidB[(size_t)row * Hc + kb + c4 * 4];
                float4 vv;
                vv.x = fmaxf(a.x + bb.x, 0.f);
                vv.y = fmaxf(a.y + bb.y, 0.f);
                vv.z = fmaxf(a.z + bb.z, 0.f);
                vv.w = fmaxf(a.w + bb.w, 0.f);
                *(float4*)&s->u.ph.As[row][c4 * 4] = vv;
            }
            stageW<8, 0>(Wemb, Hc, kb, tile, s);
        }
        __syncthreads();
        mm8(acc, s);
    }
    int t0 = threadIdx.x;
    int r = t0 & 7, b = t0 >> 3;
    int j = tile * 8 + r;
    outL[((size_t)b * Tc + t) * Vc + j] = hsum2(acc[0]) + hsum2(acc[1]) + bcls[j];
}

// ---------------- precompute 64x64 GEMM tile ----------------
__device__ __forceinline__ void storeC(float* C, size_t idx, float v) { C[idx] = v; }
__device__ __forceinline__ void storeC(__nv_bfloat16* C, size_t idx, float v) {
    C[idx] = __float2bfloat16(v);
}

template<class OUT>
__device__ void gemm_tile(const float* __restrict__ A, const float* __restrict__ W,
                          const float* __restrict__ b1, const float* __restrict__ b2,
                          OUT* __restrict__ C, int M, int N, int K, int m0, int n0, Smem* s) {
    int tid = threadIdx.x;
    int tx = tid & 15, ty = tid >> 4;            // ty in [0,32): row-pair
    float acc[2][4] = {};
    for (int kb = 0; kb < K; kb += 16) {
        __syncthreads();
        #pragma unroll
        for (int u2 = 0; u2 < 2; u2++) {
            int i = tid + u2 * NTHR;             // 1024 scalars... 64 rows x 16 k
            int r = i >> 4, kk = i & 15;
            int ra = m0 + r; if (ra >= M) ra = M - 1;
            s->u.gm.As[kk][r] = A[(size_t)ra * K + kb + kk];
            s->u.gm.Ws[kk][r] = W[(size_t)(n0 + r) * K + kb + kk];
        }
        __syncthreads();
        #pragma unroll
        for (int kk = 0; kk < 16; kk++) {
            float a0 = s->u.gm.As[kk][ty * 2];
            float a1 = s->u.gm.As[kk][ty * 2 + 1];
            float4 w4 = *(const float4*)&s->u.gm.Ws[kk][tx * 4];
            float wr[4] = {w4.x, w4.y, w4.z, w4.w};
            #pragma unroll
            for (int j = 0; j < 4; j++) {
                acc[0][j] += a0 * wr[j];
                acc[1][j] += a1 * wr[j];
            }
        }
    }
    __syncthreads();
    #pragma unroll
    for (int i = 0; i < 2; i++) {
        int row = m0 + ty * 2 + i;
        if (row < M) {
            #pragma unroll
            for (int j = 0; j < 4; j++) {
                int col = n0 + tx * 4 + j;
                float v = acc[i][j] + b1[col];
                if (b2) v += b2[col];
                storeC(C, (size_t)row * N + col, v);
            }
        }
    }
}

// ---------------- persistent kernel ----------------
__global__ void __launch_bounds__(NTHR, 1)
decoder_kernel(const float* __restrict__ enc, const int* __restrict__ y,
               const float* __restrict__ Wemb,
               const float* __restrict__ Wih1, const float* __restrict__ bih1,
               const float* __restrict__ Whh1, const float* __restrict__ bhh1,
               const float* __restrict__ Wih2, const float* __restrict__ bih2,
               const float* __restrict__ Whh2, const float* __restrict__ bhh2,
               const float* __restrict__ Wq,  const float* __restrict__ bq,
               const float* __restrict__ Wk,  const float* __restrict__ bk,
               const float* __restrict__ Wv,  const float* __restrict__ bv,
               const float* __restrict__ W1,  const float* __restrict__ b1,
               const float* __restrict__ bcls,
               float* __restrict__ outL, float* __restrict__ attnB,
               int attnBS, int attnTS)
{
    __shared__ Smem s;
    int tid = threadIdx.x;

    for (int i = blockIdx.x * NTHR + tid; i < BH; i += NBLK * NTHR) {
        g_h1[i] = 0.f; g_c1[i] = 0.f; g_h2[i] = 0.f; g_c2[i] = 0.f;
    }
    gsync();

    // precompute: K (fp32), V (bf16), LSTM1 x-side token table (fp32)
    {
        const int nKt = (Bc * Sc / 64) * (KQc / 64);   // 2048
        const int nVt = (Bc * Sc / 64) * (Ec / 64);    // 4096
        const int nEt = 16 * (4 * Hc / 64);            // 512
        for (int idx = blockIdx.x; idx < nKt + nVt + nEt; idx += NBLK) {
            if (idx < nKt) {
                int m0 = (idx / (KQc / 64)) * 64, n0 = (idx % (KQc / 64)) * 64;
                gemm_tile(enc, Wk, bk, (const float*)0, g_k, Bc * Sc, KQc, Ec, m0, n0, &s);
            } else if (idx < nKt + nVt) {
                int i2 = idx - nKt;
                int m0 = (i2 / (Ec / 64)) * 64, n0 = (i2 % (Ec / 64)) * 64;
                gemm_tile(enc, Wv, bv, (const float*)0, g_vbf, Bc * Sc, Ec, Ec, m0, n0, &s);
            } else {
                int i2 = idx - nKt - nVt;
                int m0 = (i2 / 32) * 64, n0 = (i2 % 32) * 64;
                gemm_tile(Wemb, Wih1, bih1, bhh1, g_emb1, Vc, 4 * Hc, Hc, m0, n0, &s);
            }
        }
    }
    gsync();

    for (int t = 0; t < Tc; t++) {
        int cur = t & 1, nxt = cur ^ 1;

        // P1: LSTM1 (h-side GEMM; x-side from token table)
        lstm_phase<false>(g_h1 + cur * BH, g_c1 + cur * BH,
                          g_h1 + nxt * BH, g_c1 + nxt * BH,
                          (const float*)0, y, t, (const float*)0, Whh1,
                          (const float*)0, (const float*)0, &s);
        gsync();

        // P2: LSTM2 (h-side + x-side = new h1)
        lstm_phase<true>(g_h2 + cur * BH, g_c2 + cur * BH,
                         g_h2 + nxt * BH, g_c2 + nxt * BH,
                         g_h1 + nxt * BH, y, t, Wih2, Whh2, bih2, bhh2, &s);
        gsync();

        // P3: qattn (blocks 0..63) || hidA (blocks 64..127)
        if (blockIdx.x < Bc)
            qattn_phase(blockIdx.x, g_h2 + nxt * BH, Wq, bq,
                        attnB + (size_t)blockIdx.x * attnBS + (size_t)t * attnTS, &s);
        else
            hidA_phase(g_h2 + nxt * BH, W1, b1, &s);
        gsync();

        // P4: hidB (ctx part)
        hidB_phase(W1, &s);
        gsync();

        // P5: logits (no trailing barrier: next P1 touches disjoint state;
        //     P2(t+1) starts only after the P1(t+1) barrier, which implies all
        //     blocks have finished P5(t))
        logits_phase(Wemb, bcls, outL, t, &s);
    }
}

// ---------------- launch ----------------
extern "C" void kernel_launch(void* const* d_in, const int* in_sizes, int n_in,
                              void* d_out, int out_size) {
    const float* enc   = (const float*)d_in[0];
    const int*   y     = (const int*)  d_in[1];
    const float* Wemb  = (const float*)d_in[2];
    const float* Wih1  = (const float*)d_in[3];
    const float* bih1  = (const float*)d_in[4];
    const float* Whh1  = (const float*)d_in[5];
    const float* bhh1  = (const float*)d_in[6];
    const float* Wih2  = (const float*)d_in[7];
    const float* bih2  = (const float*)d_in[8];
    const float* Whh2  = (const float*)d_in[9];
    const float* bhh2  = (const float*)d_in[10];
    const float* Wq    = (const float*)d_in[11];
    const float* bq    = (const float*)d_in[12];
    const float* Wk    = (const float*)d_in[13];
    const float* bk    = (const float*)d_in[14];
    const float* Wv    = (const float*)d_in[15];
    const float* bv    = (const float*)d_in[16];
    const float* W1    = (const float*)d_in[17];
    const float* b1    = (const float*)d_in[18];
    const float* bcls  = (const float*)d_in[19];

    float* outL = (float*)d_out;
    long long need = (long long)Bc * Tc * Vc + (long long)Bc * Tc * Sc;

    float* attnB; int attnBS, attnTS;
    if ((long long)out_size >= need) {
        attnB = outL + (size_t)Bc * Tc * Vc;
        attnBS = Tc * Sc; attnTS = Sc;
    } else {
        cudaGetSymbolAddress((void**)&attnB, g_attn_dummy);
        attnBS = Sc; attnTS = 0;
    }

    decoder_kernel<<<NBLK, NTHR>>>(enc, y, Wemb, Wih1, bih1, Whh1, bhh1,
                                   Wih2, bih2, Whh2, bhh2, Wq, bq, Wk, bk,
                                   Wv, bv, W1, b1, bcls, outL, attnB, attnBS, attnTS);
}

// round 7
// speedup vs baseline: 3.3909x; 1.3870x over previous
#include <cuda_runtime.h>
#include <cuda_fp16.h>
#include <math.h>

#define Bc  64
#define Sc  512
#define Tc  256
#define Ec  512
#define Hc  512
#define KQc 256
#define Vc  1000
#define BH  (Bc*Hc)
#define NBLK 128
#define NTHR 512

typedef unsigned long long u64t;

// ---------------- dynamic smem layout (float offsets) ----------------
#define OFF_WL1   0                      // Whh1 tile: 16 x 516
#define OFF_WL2H  8256                   // Whh2 tile: 16 x 516
#define OFF_WL2X  16512                  // Wih2 tile: 16 x 516
#define OFF_WHID  24768                  // W1 rows:    4 x 1028 (full K=1024)
#define OFF_WLOG  28880                  // Wemb rows:  8 x 516
#define OFF_WQ    33008                  // Wq rows:    2 x 516
#define OFF_AB    34040                  // A double buffer: 2 x 64 x 72
#define OFF_RED   43256                  // reduction: 32 x 66
#define SMEM_F    45368
#define SMEM_BYTES (SMEM_F * 4)          // 181472 B

// ---------------- device scratch ----------------
__device__ float  g_k[(size_t)Bc*Sc*KQc];      // K cache fp32
__device__ __half g_vh[(size_t)Bc*Sc*Ec];      // V cache fp16
__device__ float  g_emb1[(size_t)Vc*4*Hc];     // token -> LSTM1 x-side gate preacts (+biases)
__device__ float  g_h1[2*BH], g_c1[2*BH], g_h2[2*BH], g_c2[2*BH];
__device__ float  g_q[Bc*KQc];
__device__ float  g_ctx[Bc*Ec];
__device__ float  g_hid[Bc*Hc];
__device__ float  g_attn_dummy[Bc*Sc];

// ---------------- software grid barrier (replay-safe) ----------------
__device__ volatile unsigned g_bar_gen;
__device__ unsigned g_bar_cnt;

__device__ __forceinline__ void gsync() {
    __syncthreads();
    if (threadIdx.x == 0) {
        unsigned gen = g_bar_gen;
        __threadfence();
        if (atomicAdd(&g_bar_cnt, 1u) == NBLK - 1) {
            g_bar_cnt = 0u;
            __threadfence();
            g_bar_gen = gen + 1u;
        } else {
            while (g_bar_gen == gen) { }
        }
        __threadfence();
    }
    __syncthreads();
}

// ---------------- f32x2 packed FMA ----------------
__device__ __forceinline__ u64t fma2(u64t a, u64t b, u64t c) {
    u64t d;
    asm("fma.rn.f32x2 %0, %1, %2, %3;" : "=l"(d) : "l"(a), "l"(b), "l"(c));
    return d;
}
__device__ __forceinline__ float hsum2(u64t v) {
    return __uint_as_float((unsigned)v) + __uint_as_float((unsigned)(v >> 32));
}

// ---------------- GEMM inner chunk ----------------
// Thread (r0 = tid%JG, b0 = 2*((tid/JG)%32), ks = tid/(32*JG)) computes smem-W rows
// {r0, r0+JG} x batches {b0, b0+1} over its k-slice [ks*4JG, (ks+1)*4JG) of a 64-chunk.
template<int JG>
__device__ __forceinline__ void mm_chunk(u64t* acc, const float* __restrict__ wch, int padw,
                                         const float* __restrict__ ab) {
    const int KPT = 4 * JG;
    int tid = threadIdx.x;
    int r0 = tid & (JG - 1);
    int b0 = ((tid / JG) & 31) * 2;
    int ks = tid / (JG * 32);
    const float* w0 = wch + r0 * padw + ks * KPT;
    const float* w1 = w0 + JG * padw;
    const float* a0 = ab + b0 * 72 + ks * KPT;
    const float* a1 = a0 + 72;
    #pragma unroll
    for (int kk = 0; kk < KPT; kk += 4) {
        ulonglong2 W0 = *(const ulonglong2*)(w0 + kk);
        ulonglong2 W1 = *(const ulonglong2*)(w1 + kk);
        ulonglong2 A0 = *(const ulonglong2*)(a0 + kk);
        ulonglong2 A1 = *(const ulonglong2*)(a1 + kk);
        acc[0] = fma2(A0.x, W0.x, acc[0]);
        acc[1] = fma2(A1.x, W0.x, acc[1]);
        acc[2] = fma2(A0.x, W1.x, acc[2]);
        acc[3] = fma2(A1.x, W1.x, acc[3]);
        acc[0] = fma2(A0.y, W0.y, acc[0]);
        acc[1] = fma2(A1.y, W0.y, acc[1]);
        acc[2] = fma2(A0.y, W1.y, acc[2]);
        acc[3] = fma2(A1.y, W1.y, acc[3]);
    }
}

// Stream NCH 64-chunks of A (rows ld=512; optional concat source A1 for chunks >= NCH/2),
// double-buffered staging, accumulating into acc via smem-resident W.
template<int JG, int NCH>
__device__ __forceinline__ void gemm_stream(u64t* acc, const float* __restrict__ A0,
                                            const float* __restrict__ A1,
                                            const float* __restrict__ wsm, int padw, float* sm) {
    float* b0f = sm + OFF_AB;
    float* b1f = b0f + 64 * 72;
    int tid = threadIdx.x;
    int row0 = tid >> 4, c4 = (tid & 15) * 4;
    int row1 = row0 + 32;
    *(float4*)&b0f[row0 * 72 + c4] = *(const float4*)&A0[(size_t)row0 * 512 + c4];
    *(float4*)&b0f[row1 * 72 + c4] = *(const float4*)&A0[(size_t)row1 * 512 + c4];
    __syncthreads();
    #pragma unroll
    for (int i = 0; i < NCH; i++) {
        float* cur = (i & 1) ? b1f : b0f;
        float* nxt = (i & 1) ? b0f : b1f;
        float4 p0, p1;
        if (i + 1 < NCH) {
            int j = i + 1;
            const float* As = (A1 == nullptr || j < NCH / 2) ? A0 + j * 64
                                                             : A1 + (j - NCH / 2) * 64;
            p0 = *(const float4*)&As[(size_t)row0 * 512 + c4];
            p1 = *(const float4*)&As[(size_t)row1 * 512 + c4];
        }
        mm_chunk<JG>(acc, wsm + i * 64, padw, cur);
        if (i + 1 < NCH) {
            *(float4*)&nxt[row0 * 72 + c4] = p0;
            *(float4*)&nxt[row1 * 72 + c4] = p1;
        }
        __syncthreads();
    }
}

// Write per-thread partials into red[32][66]; row index = ks*2JG + r.
template<int JG>
__device__ __forceinline__ void red_write(const u64t* acc, float* red) {
    int tid = threadIdx.x;
    int r0 = tid & (JG - 1);
    int b0 = ((tid / JG) & 31) * 2;
    int ks = tid / (JG * 32);
    red[(ks * 2 * JG + r0) * 66 + b0]          = hsum2(acc[0]);
    red[(ks * 2 * JG + r0) * 66 + b0 + 1]      = hsum2(acc[1]);
    red[(ks * 2 * JG + r0 + JG) * 66 + b0]     = hsum2(acc[2]);
    red[(ks * 2 * JG + r0 + JG) * 66 + b0 + 1] = hsum2(acc[3]);
}

// ---------------- LSTM phase (16 W rows resident; JG=8, KS=2) ----------------
template<bool HASX>
__device__ void lstm_phase(const float* __restrict__ hin, const float* __restrict__ cin,
                           float* __restrict__ hout, float* __restrict__ cout,
                           const float* __restrict__ xsrc, const int* __restrict__ y, int t,
                           const float* __restrict__ bih, const float* __restrict__ bhh,
                           const float* whsm, const float* wxsm, float* sm) {
    int tile = blockIdx.x;
    u64t acc[4] = {0ull, 0ull, 0ull, 0ull};
    gemm_stream<8, 8>(acc, hin, nullptr, whsm, 516, sm);
    if (HASX) gemm_stream<8, 8>(acc, xsrc, nullptr, wxsm, 516, sm);
    float* red = sm + OFF_RED;
    red_write<8>(acc, red);
    __syncthreads();
    int u = threadIdx.x;
    if (u < 256) {
        int jj = u & 3, b = u >> 2;
        int j = tile * 4 + jj;
        float p[4];
        #pragma unroll
        for (int g = 0; g < 4; g++) {
            int r = g * 4 + jj;
            p[g] = red[r * 66 + b] + red[(16 + r) * 66 + b];
        }
        if (!HASX) {
            int tok = (t == 0) ? 0 : y[b * Tc + t - 1];
            const float* e = g_emb1 + (size_t)tok * (4 * Hc);
            p[0] += e[j]; p[1] += e[Hc + j]; p[2] += e[2 * Hc + j]; p[3] += e[3 * Hc + j];
        } else {
            p[0] += bih[j]          + bhh[j];
            p[1] += bih[Hc + j]     + bhh[Hc + j];
            p[2] += bih[2 * Hc + j] + bhh[2 * Hc + j];
            p[3] += bih[3 * Hc + j] + bhh[3 * Hc + j];
        }
        float si = 1.f / (1.f + __expf(-p[0]));
        float sf = 1.f / (1.f + __expf(-p[1]));
        float so = 1.f / (1.f + __expf(-p[3]));
        float cN = sf * cin[b * Hc + j] + si * tanhf(p[2]);
        float hN = so * tanhf(cN);
        hout[b * Hc + j] = hN;
        cout[b * Hc + j] = cN;
    }
}

// ---------------- q phase (2 Wq rows resident; JG=1, KS=16) ----------------
__device__ void q_phase(const float* __restrict__ h2n, const float* __restrict__ bq, float* sm) {
    u64t acc[4] = {0ull, 0ull, 0ull, 0ull};
    gemm_stream<1, 8>(acc, h2n, nullptr, sm + OFF_WQ, 516, sm);
    float* red = sm + OFF_RED;
    red_write<1>(acc, red);
    __syncthreads();
    int u = threadIdx.x;
    if (u < 128) {
        int jl = u & 1, b = u >> 1;
        float sum = bq[blockIdx.x * 2 + jl];
        #pragma unroll
        for (int ks = 0; ks < 16; ks++) sum += red[(ks * 2 + jl) * 66 + b];
        g_q[b * KQc + blockIdx.x * 2 + jl] = sum;
    }
}

// ---------------- attention (blocks 0..63; scores/softmax/ctx) ----------------
struct AttnS {
    float qs[KQc];
    float sc[Sc];
    float ctxp[Ec];
    float red[16];
    float red2[16];
};

__device__ void attn_phase(int b, float* __restrict__ attn_out, float* sm) {
    AttnS* at = (AttnS*)(sm + OFF_AB);
    int tid = threadIdx.x, warp = tid >> 5, lane = tid & 31;

    if (tid < KQc) at->qs[tid] = g_q[b * KQc + tid];
    __syncthreads();

    float qr[8];
    #pragma unroll
    for (int u2 = 0; u2 < 8; u2++) qr[u2] = at->qs[lane * 8 + u2];

    for (int ss = warp; ss < Sc; ss += 16) {
        const float* kr = g_k + ((size_t)b * Sc + ss) * KQc + lane * 8;
        float4 k0 = *(const float4*)kr;
        float4 k1 = *(const float4*)(kr + 4);
        float sum = qr[0]*k0.x + qr[1]*k0.y + qr[2]*k0.z + qr[3]*k0.w
                  + qr[4]*k1.x + qr[5]*k1.y + qr[6]*k1.z + qr[7]*k1.w;
        #pragma unroll
        for (int o = 16; o; o >>= 1) sum += __shfl_down_sync(~0u, sum, o);
        if (lane == 0) at->sc[ss] = sum * 0.0625f;     // 1/sqrt(256)
    }
    __syncthreads();

    float v = at->sc[tid];
    float m = v;
    #pragma unroll
    for (int o = 16; o; o >>= 1) m = fmaxf(m, __shfl_xor_sync(~0u, m, o));
    if (lane == 0) at->red[warp] = m;
    __syncthreads();
    float mm = at->red[0];
    #pragma unroll
    for (int w = 1; w < 16; w++) mm = fmaxf(mm, at->red[w]);
    float e = __expf(v - mm);
    float ssum = e;
    #pragma unroll
    for (int o = 16; o; o >>= 1) ssum += __shfl_xor_sync(~0u, ssum, o);
    if (lane == 0) at->red2[warp] = ssum;
    __syncthreads();
    float Z = 0.f;
    #pragma unroll
    for (int w = 0; w < 16; w++) Z += at->red2[w];
    float p = e / Z;
    at->sc[tid] = p;
    attn_out[tid] = p;
    __syncthreads();

    // ctx: 2-way s-split, e-pair per thread, fp16 V
    int half = tid >> 8;
    int e2 = (tid & 255) * 2;
    const __half* vb = g_vh + (size_t)b * Sc * Ec + e2;
    float ax = 0.f, ay = 0.f;
    int s0 = half * 256;
    #pragma unroll 8
    for (int ss2 = 0; ss2 < 256; ss2++) {
        float pp = at->sc[s0 + ss2];
        float2 vv = __half22float2(*(const __half2*)(vb + (size_t)(s0 + ss2) * Ec));
        ax += pp * vv.x; ay += pp * vv.y;
    }
    if (half == 1) { at->ctxp[e2] = ax; at->ctxp[e2 + 1] = ay; }
    __syncthreads();
    if (half == 0) {
        g_ctx[b * Ec + e2]     = ax + at->ctxp[e2];
        g_ctx[b * Ec + e2 + 1] = ay + at->ctxp[e2 + 1];
    }
}

// ---------------- hid = relu([h2|ctx] @ W1^T + b1) (4 rows, K=1024; JG=2, KS=8) ----------------
__device__ void hid_phase(const float* __restrict__ h2n, const float* __restrict__ b1, float* sm) {
    u64t acc[4] = {0ull, 0ull, 0ull, 0ull};
    gemm_stream<2, 16>(acc, h2n, g_ctx, sm + OFF_WHID, 1028, sm);
    float* red = sm + OFF_RED;
    red_write<2>(acc, red);
    __syncthreads();
    int u = threadIdx.x;
    if (u < 256) {
        int jl = u & 3, b = u >> 2;
        int j = blockIdx.x * 4 + jl;
        float sum = b1[j];
        #pragma unroll
        for (int ks = 0; ks < 8; ks++) sum += red[(ks * 4 + jl) * 66 + b];
        g_hid[(size_t)b * Hc + j] = fmaxf(sum, 0.f);
    }
}

// ---------------- logits (8 Wemb rows, K=512; JG=4, KS=4; blocks 0..124) ----------------
__device__ void logits_phase(const float* __restrict__ bcls, float* __restrict__ outL,
                             int t, float* sm) {
    u64t acc[4] = {0ull, 0ull, 0ull, 0ull};
    gemm_stream<4, 8>(acc, g_hid, nullptr, sm + OFF_WLOG, 516, sm);
    float* red = sm + OFF_RED;
    red_write<4>(acc, red);
    __syncthreads();
    int u = threadIdx.x;
    int jl = u & 7, b = u >> 3;
    int j = blockIdx.x * 8 + jl;
    float sum = bcls[j];
    #pragma unroll
    for (int ks = 0; ks < 4; ks++) sum += red[(ks * 8 + jl) * 66 + b];
    outL[((size_t)b * Tc + t) * Vc + j] = sum;
}

// ---------------- weight preload (once per launch) ----------------
__device__ void preload_weights(float* sm, const float* __restrict__ Whh1,
                                const float* __restrict__ Whh2, const float* __restrict__ Wih2,
                                const float* __restrict__ W1, const float* __restrict__ Wemb,
                                const float* __restrict__ Wq) {
    int tid = threadIdx.x;
    int tile = blockIdx.x;
    for (int i = tid; i < 16 * 128; i += NTHR) {          // 16 rows x 512 as float4
        int r = i >> 7, c4 = (i & 127) * 4;
        int srow = (r >> 2) * Hc + tile * 4 + (r & 3);
        *(float4*)&sm[OFF_WL1 + r * 516 + c4]  = *(const float4*)&Whh1[(size_t)srow * Hc + c4];
        *(float4*)&sm[OFF_WL2H + r * 516 + c4] = *(const float4*)&Whh2[(size_t)srow * Hc + c4];
        *(float4*)&sm[OFF_WL2X + r * 516 + c4] = *(const float4*)&Wih2[(size_t)srow * Hc + c4];
    }
    for (int i = tid; i < 4 * 256; i += NTHR) {           // 4 rows x 1024
        int r = i >> 8, c4 = (i & 255) * 4;
        *(float4*)&sm[OFF_WHID + r * 1028 + c4] =
            *(const float4*)&W1[(size_t)(tile * 4 + r) * (Hc + Ec) + c4];
    }
    if (tile < Vc / 8)
        for (int i = tid; i < 8 * 128; i += NTHR) {       // 8 rows x 512
            int r = i >> 7, c4 = (i & 127) * 4;
            *(float4*)&sm[OFF_WLOG + r * 516 + c4] =
                *(const float4*)&Wemb[(size_t)(tile * 8 + r) * Hc + c4];
        }
    for (int i = tid; i < 2 * 128; i += NTHR) {           // 2 rows x 512
        int r = i >> 7, c4 = (i & 127) * 4;
        *(float4*)&sm[OFF_WQ + r * 516 + c4] =
            *(const float4*)&Wq[(size_t)(tile * 2 + r) * Hc + c4];
    }
}

// ---------------- precompute 64x64 GEMM tile ----------------
__device__ __forceinline__ void storeC(float* C, size_t idx, float v) { C[idx] = v; }
__device__ __forceinline__ void storeC(__half* C, size_t idx, float v) { C[idx] = __float2half(v); }

template<class OUT>
__device__ void gemm_tile(const float* __restrict__ A, const float* __restrict__ W,
                          const float* __restrict__ b1v, const float* __restrict__ b2v,
                          OUT* __restrict__ C, int M, int N, int K, int m0, int n0, float* sm) {
    float* As = sm + OFF_AB;                    // [16][68]
    float* Ws = As + 16 * 68;                   // [16][68]
    int tid = threadIdx.x;
    int tx = tid & 15, ty = tid >> 4;           // ty in [0,32): row-pair
    float acc[2][4] = {};
    for (int kb = 0; kb < K; kb += 16) {
        __syncthreads();
        #pragma unroll
        for (int u2 = 0; u2 < 2; u2++) {
            int i = tid + u2 * NTHR;
            int r = i >> 4, kk = i & 15;
            int ra = m0 + r; if (ra >= M) ra = M - 1;
            As[kk * 68 + r] = A[(size_t)ra * K + kb + kk];
            Ws[kk * 68 + r] = W[(size_t)(n0 + r) * K + kb + kk];
        }
        __syncthreads();
        #pragma unroll
        for (int kk = 0; kk < 16; kk++) {
            float a0 = As[kk * 68 + ty * 2];
            float a1 = As[kk * 68 + ty * 2 + 1];
            float4 w4 = *(const float4*)&Ws[kk * 68 + tx * 4];
            float wr[4] = {w4.x, w4.y, w4.z, w4.w};
            #pragma unroll
            for (int jv = 0; jv < 4; jv++) {
                acc[0][jv] += a0 * wr[jv];
                acc[1][jv] += a1 * wr[jv];
            }
        }
    }
    __syncthreads();
    #pragma unroll
    for (int i = 0; i < 2; i++) {
        int row = m0 + ty * 2 + i;
        if (row < M) {
            #pragma unroll
            for (int jv = 0; jv < 4; jv++) {
                int col = n0 + tx * 4 + jv;
                float vv = acc[i][jv] + b1v[col];
                if (b2v) vv += b2v[col];
                storeC(C, (size_t)row * N + col, vv);
            }
        }
    }
}

// ---------------- persistent kernel ----------------
__global__ void __launch_bounds__(NTHR, 1)
decoder_kernel(const float* __restrict__ enc, const int* __restrict__ y,
               const float* __restrict__ Wemb,
               const float* __restrict__ Wih1, const float* __restrict__ bih1,
               const float* __restrict__ Whh1, const float* __restrict__ bhh1,
               const float* __restrict__ Wih2, const float* __restrict__ bih2,
               const float* __restrict__ Whh2, const float* __restrict__ bhh2,
               const float* __restrict__ Wq,  const float* __restrict__ bq,
               const float* __restrict__ Wk,  const float* __restrict__ bk,
               const float* __restrict__ Wv,  const float* __restrict__ bv,
               const float* __restrict__ W1,  const float* __restrict__ b1,
               const float* __restrict__ bcls,
               float* __restrict__ outL, float* __restrict__ attnB,
               int attnBS, int attnTS)
{
    extern __shared__ float sm[];
    int tid = threadIdx.x;

    for (int i = blockIdx.x * NTHR + tid; i < BH; i += NBLK * NTHR) {
        g_h1[i] = 0.f; g_c1[i] = 0.f; g_h2[i] = 0.f; g_c2[i] = 0.f;
    }
    preload_weights(sm, Whh1, Whh2, Wih2, W1, Wemb, Wq);
    gsync();

    // precompute: K (fp32), V (fp16), LSTM1 x-side token table (fp32)
    {
        const int nKt = (Bc * Sc / 64) * (KQc / 64);   // 2048
        const int nVt = (Bc * Sc / 64) * (Ec / 64);    // 4096
        const int nEt = 16 * (4 * Hc / 64);            // 512
        for (int idx = blockIdx.x; idx < nKt + nVt + nEt; idx += NBLK) {
            if (idx < nKt) {
                int m0 = (idx / (KQc / 64)) * 64, n0 = (idx % (KQc / 64)) * 64;
                gemm_tile(enc, Wk, bk, (const float*)0, g_k, Bc * Sc, KQc, Ec, m0, n0, sm);
            } else if (idx < nKt + nVt) {
                int i2 = idx - nKt;
                int m0 = (i2 / (Ec / 64)) * 64, n0 = (i2 % (Ec / 64)) * 64;
                gemm_tile(enc, Wv, bv, (const float*)0, g_vh, Bc * Sc, Ec, Ec, m0, n0, sm);
            } else {
                int i2 = idx - nKt - nVt;
                int m0 = (i2 / 32) * 64, n0 = (i2 % 32) * 64;
                gemm_tile(Wemb, Wih1, bih1, bhh1, g_emb1, Vc, 4 * Hc, Hc, m0, n0, sm);
            }
        }
    }
    gsync();

    for (int t = 0; t < Tc; t++) {
        int cur = t & 1, nxt = cur ^ 1;

        // P1: LSTM1 (h-side GEMM; x-side from token table)
        lstm_phase<false>(g_h1 + cur * BH, g_c1 + cur * BH,
                          g_h1 + nxt * BH, g_c1 + nxt * BH,
                          (const float*)0, y, t, (const float*)0, (const float*)0,
                          sm + OFF_WL1, (const float*)0, sm);
        gsync();

        // P2: LSTM2 (h-side + x-side = new h1)
        lstm_phase<true>(g_h2 + cur * BH, g_c2 + cur * BH,
                         g_h2 + nxt * BH, g_c2 + nxt * BH,
                         g_h1 + nxt * BH, y, t, bih2, bhh2,
                         sm + OFF_WL2H, sm + OFF_WL2X, sm);
        gsync();

        // P3a: q = h2 @ Wq^T + bq (all blocks, resident Wq rows)
        q_phase(g_h2 + nxt * BH, bq, sm);
        gsync();

        // P3: attention (blocks 0..63)
        if (blockIdx.x < Bc)
            attn_phase(blockIdx.x,
                       attnB + (size_t)blockIdx.x * attnBS + (size_t)t * attnTS, sm);
        gsync();

        // P4: hid = relu([h2|ctx] @ W1^T + b1)
        hid_phase(g_h2 + nxt * BH, b1, sm);
        gsync();

        // P5: logits (no trailing barrier: P1(t+1) touches only h1/c1/emb1, disjoint;
        //     P2(t+1) starts after the P1 barrier, which implies all blocks left P5(t))
        if (blockIdx.x < Vc / 8)
            logits_phase(bcls, outL, t, sm);
    }
}

// ---------------- launch ----------------
extern "C" void kernel_launch(void* const* d_in, const int* in_sizes, int n_in,
                              void* d_out, int out_size) {
    const float* enc   = (const float*)d_in[0];
    const int*   y     = (const int*)  d_in[1];
    const float* Wemb  = (const float*)d_in[2];
    const float* Wih1  = (const float*)d_in[3];
    const float* bih1  = (const float*)d_in[4];
    const float* Whh1  = (const float*)d_in[5];
    const float* bhh1  = (const float*)d_in[6];
    const float* Wih2  = (const float*)d_in[7];
    const float* bih2  = (const float*)d_in[8];
    const float* Whh2  = (const float*)d_in[9];
    const float* bhh2  = (const float*)d_in[10];
    const float* Wq    = (const float*)d_in[11];
    const float* bq    = (const float*)d_in[12];
    const float* Wk    = (const float*)d_in[13];
    const float* bk    = (const float*)d_in[14];
    const float* Wv    = (const float*)d_in[15];
    const float* bv    = (const float*)d_in[16];
    const float* W1    = (const float*)d_in[17];
    const float* b1    = (const float*)d_in[18];
    const float* bcls  = (const float*)d_in[19];

    float* outL = (float*)d_out;
    long long need = (long long)Bc * Tc * Vc + (long long)Bc * Tc * Sc;

    float* attnB; int attnBS, attnTS;
    if ((long long)out_size >= need) {
        attnB = outL + (size_t)Bc * Tc * Vc;
        attnBS = Tc * Sc; attnTS = Sc;
    } else {
        cudaGetSymbolAddress((void**)&attnB, g_attn_dummy);
        attnBS = Sc; attnTS = 0;
    }

    cudaFuncSetAttribute(decoder_kernel,
                         cudaFuncAttributeMaxDynamicSharedMemorySize, SMEM_BYTES);

    decoder_kernel<<<NBLK, NTHR, SMEM_BYTES>>>(enc, y, Wemb, Wih1, bih1, Whh1, bhh1,
                                               Wih2, bih2, Whh2, bhh2, Wq, bq, Wk, bk,
                                               Wv, bv, W1, b1, bcls, outL,
                                               attnB, attnBS, attnTS);
}

// round 8
// speedup vs baseline: 4.2443x; 1.2517x over previous
#include <cuda_runtime.h>
#include <cuda_fp16.h>
#include <math.h>

#define Bc  64
#define Sc  512
#define Tc  256
#define Ec  512
#define Hc  512
#define KQc 256
#define Vc  1000
#define BH  (Bc*Hc)
#define NBLK 128
#define NTHR 512

typedef unsigned long long u64t;

// ---------------- dynamic smem layout (float offsets) ----------------
#define OFF_WL1   0                      // Whh1 tile: 16 x 516
#define OFF_WL2H  8256                   // Whh2 tile: 16 x 516
#define OFF_WL2X  16512                  // Wih2 tile: 16 x 516
#define OFF_WHID  24768                  // W1 rows:   4 x 1028 (full K=1024)
#define OFF_WLOG  28880                  // Wemb rows: 8 x 516
#define OFF_AB    33008                  // A double buffer: 2 x 64 x 68 (aliased by attn)
#define OFF_RED   41712                  // reduction: 128 x 66
#define SMEM_F    50160
#define SMEM_BYTES (SMEM_F * 4)          // 200640 B

// ---------------- device scratch ----------------
__device__ __half g_kh[(size_t)Bc*Sc*KQc];     // K cache fp16
__device__ __half g_vh[(size_t)Bc*Sc*Ec];      // V cache fp16
__device__ __half g_wqh[KQc*Hc];               // Wq fp16
__device__ float  g_emb1[(size_t)Vc*4*Hc];     // token -> LSTM1 x-side gate preacts (+biases)
__device__ float  g_h1[2*BH], g_c1[2*BH], g_h2[2*BH], g_c2[2*BH];
__device__ float  g_ctx[Bc*Ec];
__device__ float  g_hid[Bc*Hc];
__device__ float  g_attn_dummy[Bc*Sc];

// ---------------- grid barrier: distributed flags + block0 sweep (replay-safe) ----------------
__device__ volatile unsigned g_flags[NBLK*32];
__device__ volatile unsigned g_release;

__device__ __forceinline__ void gsync(unsigned gen) {
    __syncthreads();
    if (blockIdx.x == 0) {
        int tid = threadIdx.x;
        if (tid > 0 && tid < NBLK)
            while (g_flags[tid * 32] < gen) { }
        __syncthreads();
        if (tid == 0) { __threadfence(); g_release = gen; }
    } else {
        if (threadIdx.x == 0) {
            __threadfence();
            g_flags[blockIdx.x * 32] = gen;
            while (g_release < gen) { }
            __threadfence();
        }
    }
    __syncthreads();
}

// ---------------- f32x2 packed FMA ----------------
__device__ __forceinline__ u64t fma2(u64t a, u64t b, u64t c) {
    u64t d;
    asm("fma.rn.f32x2 %0, %1, %2, %3;" : "=l"(d) : "l"(a), "l"(b), "l"(c));
    return d;
}
__device__ __forceinline__ float hsum2(u64t v) {
    return __uint_as_float((unsigned)v) + __uint_as_float((unsigned)(v >> 32));
}

// ---------------- GEMM core: broadcast-W, lane=batch, k-split ----------------
// warp = (rg, kh): rg = warp % NRG rows-group, kh = warp / NRG k-slice.
// thread: W rows rg*NRPT..+NRPT-1 (BROADCAST loads), batches {lane, lane+32}
// (conflict-free LDS.128 with pad 68), k in [kh*KPT, (kh+1)*KPT) of each 64-chunk.
template<int NROWS, int NRPT>
__device__ __forceinline__ void mm_chunk2(u64t (*acc)[2], const float* __restrict__ wch,
                                          int padw, const float* __restrict__ ab) {
    const int NRG = NROWS / NRPT;
    const int NKH = 16 / NRG;
    const int KPT = 64 / NKH;
    int warp = threadIdx.x >> 5, lane = threadIdx.x & 31;
    int rg = warp % NRG;
    int kh = warp / NRG;
    int k0 = kh * KPT;
    const float* wbase = wch + (rg * NRPT) * padw + k0;
    const float* a0 = ab + lane * 68 + k0;
    const float* a1 = ab + (lane + 32) * 68 + k0;
    #pragma unroll
    for (int kk = 0; kk < KPT; kk += 4) {
        ulonglong2 A0 = *(const ulonglong2*)(a0 + kk);
        ulonglong2 A1 = *(const ulonglong2*)(a1 + kk);
        #pragma unroll
        for (int r = 0; r < NRPT; r++) {
            ulonglong2 W = *(const ulonglong2*)(wbase + r * padw + kk);
            acc[r][0] = fma2(A0.x, W.x, acc[r][0]);
            acc[r][1] = fma2(A1.x, W.x, acc[r][1]);
            acc[r][0] = fma2(A0.y, W.y, acc[r][0]);
            acc[r][1] = fma2(A1.y, W.y, acc[r][1]);
        }
    }
}

// Stream NCH 64-chunks of A (ld = 512) through smem-resident W, double-buffered.
template<int NROWS, int NRPT, int NCH>
__device__ void gemm_stream2(u64t (*acc)[2], const float* __restrict__ A0,
                             const float* __restrict__ wsm, int padw, float* sm) {
    float* b0f = sm + OFF_AB;
    float* b1f = b0f + 64 * 68;
    int tid = threadIdx.x;
    int row0 = tid >> 4, c4 = (tid & 15) * 4;
    int row1 = row0 + 32;
    *(float4*)&b0f[row0 * 68 + c4] = *(const float4*)&A0[(size_t)row0 * 512 + c4];
    *(float4*)&b0f[row1 * 68 + c4] = *(const float4*)&A0[(size_t)row1 * 512 + c4];
    __syncthreads();
    #pragma unroll
    for (int i = 0; i < NCH; i++) {
        float* cur = (i & 1) ? b1f : b0f;
        float* nxt = (i & 1) ? b0f : b1f;
        float4 p0, p1;
        if (i + 1 < NCH) {
            p0 = *(const float4*)&A0[(size_t)row0 * 512 + (i + 1) * 64 + c4];
            p1 = *(const float4*)&A0[(size_t)row1 * 512 + (i + 1) * 64 + c4];
        }
        mm_chunk2<NROWS, NRPT>(acc, wsm + i * 64, padw, cur);
        if (i + 1 < NCH) {
            *(float4*)&nxt[row0 * 68 + c4] = p0;
            *(float4*)&nxt[row1 * 68 + c4] = p1;
        }
        __syncthreads();
    }
}

template<int NROWS, int NRPT>
__device__ __forceinline__ void red_write2(u64t (*acc)[2], float* red) {
    const int NRG = NROWS / NRPT;
    int warp = threadIdx.x >> 5, lane = threadIdx.x & 31;
    int rg = warp % NRG, kh = warp / NRG;
    #pragma unroll
    for (int r = 0; r < NRPT; r++) {
        int rr = kh * NROWS + rg * NRPT + r;
        red[rr * 66 + lane]      = hsum2(acc[r][0]);
        red[rr * 66 + lane + 32] = hsum2(acc[r][1]);
    }
}

// ---------------- LSTM phase (NROWS=16, NRPT=8, NKH=8) ----------------
template<bool HASX>
__device__ void lstm_phase(const float* __restrict__ hin, const float* __restrict__ cin,
                           float* __restrict__ hout, float* __restrict__ cout,
                           const float* __restrict__ xsrc, const int* __restrict__ y, int t,
                           const float* __restrict__ bih, const float* __restrict__ bhh,
                           const float* whsm, const float* wxsm, float* sm) {
    int tile = blockIdx.x;
    u64t acc[8][2] = {};
    gemm_stream2<16, 8, 8>(acc, hin, whsm, 516, sm);
    if (HASX) gemm_stream2<16, 8, 8>(acc, xsrc, wxsm, 516, sm);
    float* red = sm + OFF_RED;
    red_write2<16, 8>(acc, red);
    __syncthreads();
    int u = threadIdx.x;
    if (u < 256) {
        int jj = u & 3, b = u >> 2;
        int j = tile * 4 + jj;
        float p[4] = {0.f, 0.f, 0.f, 0.f};
        #pragma unroll
        for (int kh = 0; kh < 8; kh++)
            #pragma unroll
            for (int g = 0; g < 4; g++)
                p[g] += red[(kh * 16 + g * 4 + jj) * 66 + b];
        if (!HASX) {
            int tok = (t == 0) ? 0 : y[b * Tc + t - 1];
            const float* e = g_emb1 + (size_t)tok * (4 * Hc);
            p[0] += e[j]; p[1] += e[Hc + j]; p[2] += e[2 * Hc + j]; p[3] += e[3 * Hc + j];
        } else {
            p[0] += bih[j]          + bhh[j];
            p[1] += bih[Hc + j]     + bhh[Hc + j];
            p[2] += bih[2 * Hc + j] + bhh[2 * Hc + j];
            p[3] += bih[3 * Hc + j] + bhh[3 * Hc + j];
        }
        float si = 1.f / (1.f + __expf(-p[0]));
        float sf = 1.f / (1.f + __expf(-p[1]));
        float so = 1.f / (1.f + __expf(-p[3]));
        float cN = sf * cin[b * Hc + j] + si * tanhf(p[2]);
        float hN = so * tanhf(cN);
        hout[b * Hc + j] = hN;
        cout[b * Hc + j] = cN;
    }
}

// ---------------- fused q + attention (blocks 0..63) ----------------
struct AttnS {
    float qh[512];
    float qs[KQc];
    float sc[Sc];
    float ctxp[3 * 512];
    float red[16];
    float red2[16];
};

__device__ __forceinline__ float dot8h(const float* qr, uint4 pk) {
    const __half2* p2 = (const __half2*)&pk;
    float s = 0.f;
    #pragma unroll
    for (int q = 0; q < 4; q++) {
        float2 f = __half22float2(p2[q]);
        s += qr[q * 2] * f.x + qr[q * 2 + 1] * f.y;
    }
    return s;
}

__device__ void qattn_phase(int b, const float* __restrict__ h2n,
                            const float* __restrict__ bq,
                            float* __restrict__ attn_out, float* sm) {
    AttnS* at = (AttnS*)(sm + OFF_AB);
    int tid = threadIdx.x, warp = tid >> 5, lane = tid & 31;

    at->qh[tid] = h2n[b * Hc + tid];
    __syncthreads();

    float hr[16];
    #pragma unroll
    for (int u2 = 0; u2 < 16; u2++) hr[u2] = at->qh[lane * 16 + u2];

    // q[j] = h2[b] . Wq[j] + bq[j]  (fp16 Wq, 2-way ILP)
    #pragma unroll
    for (int i = 0; i < 8; i++) {
        int j0 = warp + i * 32, j1 = j0 + 16;
        const __half* w0 = g_wqh + (size_t)j0 * Hc + lane * 16;
        const __half* w1 = g_wqh + (size_t)j1 * Hc + lane * 16;
        float s0 = dot8h(hr, *(const uint4*)w0) + dot8h(hr + 8, *(const uint4*)(w0 + 8));
        float s1 = dot8h(hr, *(const uint4*)w1) + dot8h(hr + 8, *(const uint4*)(w1 + 8));
        #pragma unroll
        for (int o = 16; o; o >>= 1) {
            s0 += __shfl_down_sync(~0u, s0, o);
            s1 += __shfl_down_sync(~0u, s1, o);
        }
        if (lane == 0) {
            at->qs[j0] = s0 + bq[j0];
            at->qs[j1] = s1 + bq[j1];
        }
    }
    __syncthreads();

    float qr[8];
    #pragma unroll
    for (int u2 = 0; u2 < 8; u2++) qr[u2] = at->qs[lane * 8 + u2];

    // scores (fp16 K, 2-way ILP)
    #pragma unroll
    for (int i = 0; i < 16; i++) {
        int sA = warp + i * 32, sB = sA + 16;
        const __half* kA = g_kh + ((size_t)b * Sc + sA) * KQc + lane * 8;
        const __half* kB = g_kh + ((size_t)b * Sc + sB) * KQc + lane * 8;
        float s0 = dot8h(qr, *(const uint4*)kA);
        float s1 = dot8h(qr, *(const uint4*)kB);
        #pragma unroll
        for (int o = 16; o; o >>= 1) {
            s0 += __shfl_down_sync(~0u, s0, o);
            s1 += __shfl_down_sync(~0u, s1, o);
        }
        if (lane == 0) {
            at->sc[sA] = s0 * 0.0625f;    // 1/sqrt(256)
            at->sc[sB] = s1 * 0.0625f;
        }
    }
    __syncthreads();

    // softmax over 512
    float v = at->sc[tid];
    float m = v;
    #pragma unroll
    for (int o = 16; o; o >>= 1) m = fmaxf(m, __shfl_xor_sync(~0u, m, o));
    if (lane == 0) at->red[warp] = m;
    __syncthreads();
    float mm = at->red[0];
    #pragma unroll
    for (int w = 1; w < 16; w++) mm = fmaxf(mm, at->red[w]);
    float e = __expf(v - mm);
    float ssum = e;
    #pragma unroll
    for (int o = 16; o; o >>= 1) ssum += __shfl_xor_sync(~0u, ssum, o);
    if (lane == 0) at->red2[warp] = ssum;
    __syncthreads();
    float Z = 0.f;
    #pragma unroll
    for (int w = 0; w < 16; w++) Z += at->red2[w];
    float p = e / Z;
    at->sc[tid] = p;
    attn_out[tid] = p;
    __syncthreads();

    // ctx: 4-way s-split, 4 e per thread (fp16 V, 8B loads)
    int sq = tid >> 7;
    int e4 = (tid & 127) * 4;
    const __half* vb = g_vh + (size_t)b * Sc * Ec + e4;
    float a0 = 0.f, a1 = 0.f, a2 = 0.f, a3 = 0.f;
    int sb = sq * 128;
    #pragma unroll 8
    for (int i2 = 0; i2 < 128; i2++) {
        float pp = at->sc[sb + i2];
        uint2 pk = *(const uint2*)(vb + (size_t)(sb + i2) * Ec);
        float2 f0 = __half22float2(*(__half2*)&pk.x);
        float2 f1 = __half22float2(*(__half2*)&pk.y);
        a0 += pp * f0.x; a1 += pp * f0.y; a2 += pp * f1.x; a3 += pp * f1.y;
    }
    if (sq) {
        float* cp = at->ctxp + (sq - 1) * 512 + e4;
        cp[0] = a0; cp[1] = a1; cp[2] = a2; cp[3] = a3;
    }
    __syncthreads();
    if (sq == 0) {
        #pragma unroll
        for (int q = 0; q < 3; q++) {
            const float* cp = at->ctxp + q * 512 + e4;
            a0 += cp[0]; a1 += cp[1]; a2 += cp[2]; a3 += cp[3];
        }
        float4 o = {a0, a1, a2, a3};
        *(float4*)&g_ctx[b * Ec + e4] = o;
    }
}

// ---------------- hid = relu([h2|ctx] @ W1^T + b1): all blocks, 4 rows, K=1024 ----------------
__device__ void hid_phase(const float* __restrict__ h2n, const float* __restrict__ b1, float* sm) {
    u64t acc[4][2] = {};
    gemm_stream2<4, 4, 8>(acc, h2n,  sm + OFF_WHID,       1028, sm);
    gemm_stream2<4, 4, 8>(acc, g_ctx, sm + OFF_WHID + 512, 1028, sm);
    float* red = sm + OFF_RED;
    red_write2<4, 4>(acc, red);
    __syncthreads();
    int u = threadIdx.x;
    if (u < 256) {
        int r = u & 3, b = u >> 2;
        int j = blockIdx.x * 4 + r;
        float sum = b1[j];
        #pragma unroll
        for (int kh = 0; kh < 16; kh++) sum += red[(kh * 4 + r) * 66 + b];
        g_hid[(size_t)b * Hc + j] = fmaxf(sum, 0.f);
    }
}

// ---------------- logits (blocks 0..124, 8 rows, K=512) ----------------
__device__ void logits_phase(const float* __restrict__ bcls, float* __restrict__ outL,
                             int t, float* sm) {
    u64t acc[8][2] = {};
    gemm_stream2<8, 8, 8>(acc, g_hid, sm + OFF_WLOG, 516, sm);
    float* red = sm + OFF_RED;
    red_write2<8, 8>(acc, red);
    __syncthreads();
    int u = threadIdx.x;
    int r = u & 7, b = u >> 3;
    int j = blockIdx.x * 8 + r;
    float sum = bcls[j];
    #pragma unroll
    for (int kh = 0; kh < 16; kh++) sum += red[(kh * 8 + r) * 66 + b];
    outL[((size_t)b * Tc + t) * Vc + j] = sum;
}

// ---------------- weight preload ----------------
__device__ void preload_weights(float* sm, const float* __restrict__ Whh1,
                                const float* __restrict__ Whh2, const float* __restrict__ Wih2,
                                const float* __restrict__ W1, const float* __restrict__ Wemb) {
    int tid = threadIdx.x;
    int tile = blockIdx.x;
    for (int i = tid; i < 16 * 128; i += NTHR) {
        int r = i >> 7, c4 = (i & 127) * 4;
        int srow = (r >> 2) * Hc + tile * 4 + (r & 3);
        *(float4*)&sm[OFF_WL1 + r * 516 + c4]  = *(const float4*)&Whh1[(size_t)srow * Hc + c4];
        *(float4*)&sm[OFF_WL2H + r * 516 + c4] = *(const float4*)&Whh2[(size_t)srow * Hc + c4];
        *(float4*)&sm[OFF_WL2X + r * 516 + c4] = *(const float4*)&Wih2[(size_t)srow * Hc + c4];
    }
    for (int i = tid; i < 4 * 256; i += NTHR) {
        int r = i >> 8, c4 = (i & 255) * 4;
        *(float4*)&sm[OFF_WHID + r * 1028 + c4] =
            *(const float4*)&W1[(size_t)(tile * 4 + r) * (Hc + Ec) + c4];
    }
    if (tile < Vc / 8)
        for (int i = tid; i < 8 * 128; i += NTHR) {
            int r = i >> 7, c4 = (i & 127) * 4;
            *(float4*)&sm[OFF_WLOG + r * 516 + c4] =
                *(const float4*)&Wemb[(size_t)(tile * 8 + r) * Hc + c4];
        }
}

// ---------------- precompute 64x64 GEMM tile ----------------
__device__ __forceinline__ void storeC(float* C, size_t idx, float v) { C[idx] = v; }
__device__ __forceinline__ void storeC(__half* C, size_t idx, float v) { C[idx] = __float2half(v); }

template<class OUT>
__device__ void gemm_tile(const float* __restrict__ A, const float* __restrict__ W,
                          const float* __restrict__ b1v, const float* __restrict__ b2v,
                          OUT* __restrict__ C, int M, int N, int K, int m0, int n0, float* sm) {
    float* As = sm + OFF_AB;                 // [16][68]
    float* Ws = As + 16 * 68;                // [16][68]
    int tid = threadIdx.x;
    int tx = tid & 15, ty = tid >> 4;
    float acc[2][4] = {};
    for (int kb = 0; kb < K; kb += 16) {
        __syncthreads();
        #pragma unroll
        for (int u2 = 0; u2 < 2; u2++) {
            int i = tid + u2 * NTHR;
            int r = i >> 4, kk = i & 15;
            int ra = m0 + r; if (ra >= M) ra = M - 1;
            As[kk * 68 + r] = A[(size_t)ra * K + kb + kk];
            Ws[kk * 68 + r] = W[(size_t)(n0 + r) * K + kb + kk];
        }
        __syncthreads();
        #pragma unroll
        for (int kk = 0; kk < 16; kk++) {
            float a0 = As[kk * 68 + ty * 2];
            float a1 = As[kk * 68 + ty * 2 + 1];
            float4 w4 = *(const float4*)&Ws[kk * 68 + tx * 4];
            float wr[4] = {w4.x, w4.y, w4.z, w4.w};
            #pragma unroll
            for (int jv = 0; jv < 4; jv++) {
                acc[0][jv] += a0 * wr[jv];
                acc[1][jv] += a1 * wr[jv];
            }
        }
    }
    __syncthreads();
    #pragma unroll
    for (int i = 0; i < 2; i++) {
        int row = m0 + ty * 2 + i;
        if (row < M) {
            #pragma unroll
            for (int jv = 0; jv < 4; jv++) {
                int col = n0 + tx * 4 + jv;
                float vv = acc[i][jv] + b1v[col];
                if (b2v) vv += b2v[col];
                storeC(C, (size_t)row * N + col, vv);
            }
        }
    }
}

// ---------------- persistent kernel ----------------
__global__ void __launch_bounds__(NTHR, 1)
decoder_kernel(const float* __restrict__ enc, const int* __restrict__ y,
               const float* __restrict__ Wemb,
               const float* __restrict__ Wih1, const float* __restrict__ bih1,
               const float* __restrict__ Whh1, const float* __restrict__ bhh1,
               const float* __restrict__ Wih2, const float* __restrict__ bih2,
               const float* __restrict__ Whh2, const float* __restrict__ bhh2,
               const float* __restrict__ Wq,  const float* __restrict__ bq,
               const float* __restrict__ Wk,  const float* __restrict__ bk,
               const float* __restrict__ Wv,  const float* __restrict__ bv,
               const float* __restrict__ W1,  const float* __restrict__ b1,
               const float* __restrict__ bcls,
               float* __restrict__ outL, float* __restrict__ attnB,
               int attnBS, int attnTS)
{
    extern __shared__ float sm[];
    int tid = threadIdx.x;
    unsigned gen = g_release;                  // replay-safe barrier base

    for (int i = blockIdx.x * NTHR + tid; i < BH; i += NBLK * NTHR) {
        g_h1[i] = 0.f; g_c1[i] = 0.f; g_h2[i] = 0.f; g_c2[i] = 0.f;
    }
    for (int i = blockIdx.x * NTHR + tid; i < KQc * Hc; i += NBLK * NTHR)
        g_wqh[i] = __float2half(Wq[i]);
    preload_weights(sm, Whh1, Whh2, Wih2, W1, Wemb);
    gsync(++gen);

    // precompute: K (fp16), V (fp16), LSTM1 x-side token table (fp32)
    {
        const int nKt = (Bc * Sc / 64) * (KQc / 64);   // 2048
        const int nVt = (Bc * Sc / 64) * (Ec / 64);    // 4096
        const int nEt = 16 * (4 * Hc / 64);            // 512
        for (int idx = blockIdx.x; idx < nKt + nVt + nEt; idx += NBLK) {
            if (idx < nKt) {
                int m0 = (idx / (KQc / 64)) * 64, n0 = (idx % (KQc / 64)) * 64;
                gemm_tile(enc, Wk, bk, (const float*)0, g_kh, Bc * Sc, KQc, Ec, m0, n0, sm);
            } else if (idx < nKt + nVt) {
                int i2 = idx - nKt;
                int m0 = (i2 / (Ec / 64)) * 64, n0 = (i2 % (Ec / 64)) * 64;
                gemm_tile(enc, Wv, bv, (const float*)0, g_vh, Bc * Sc, Ec, Ec, m0, n0, sm);
            } else {
                int i2 = idx - nKt - nVt;
                int m0 = (i2 / 32) * 64, n0 = (i2 % 32) * 64;
                gemm_tile(Wemb, Wih1, bih1, bhh1, g_emb1, Vc, 4 * Hc, Hc, m0, n0, sm);
            }
        }
    }
    gsync(++gen);

    for (int t = 0; t < Tc; t++) {
        int cur = t & 1, nxt = cur ^ 1;

        // P1: LSTM1 (h-side GEMM; x-side via token table)
        lstm_phase<false>(g_h1 + cur * BH, g_c1 + cur * BH,
                          g_h1 + nxt * BH, g_c1 + nxt * BH,
                          (const float*)0, y, t, (const float*)0, (const float*)0,
                          sm + OFF_WL1, (const float*)0, sm);
        gsync(++gen);

        // P2: LSTM2
        lstm_phase<true>(g_h2 + cur * BH, g_c2 + cur * BH,
                         g_h2 + nxt * BH, g_c2 + nxt * BH,
                         g_h1 + nxt * BH, y, t, bih2, bhh2,
                         sm + OFF_WL2H, sm + OFF_WL2X, sm);
        gsync(++gen);

        // P3: q + attention (blocks 0..63); others idle
        if (blockIdx.x < Bc)
            qattn_phase(blockIdx.x, g_h2 + nxt * BH, bq,
                        attnB + (size_t)blockIdx.x * attnBS + (size_t)t * attnTS, sm);
        gsync(++gen);

        // P4: hid (all blocks)
        hid_phase(g_h2 + nxt * BH, b1, sm);
        gsync(++gen);

        // P5: logits — no trailing barrier (next P1 touches disjoint state; the
        //     P1(t+1) barrier orders P5(t) before P2(t+1))
        if (blockIdx.x < Vc / 8)
            logits_phase(bcls, outL, t, sm);
    }
}

// ---------------- launch ----------------
extern "C" void kernel_launch(void* const* d_in, const int* in_sizes, int n_in,
                              void* d_out, int out_size) {
    const float* enc   = (const float*)d_in[0];
    const int*   y     = (const int*)  d_in[1];
    const float* Wemb  = (const float*)d_in[2];
    const float* Wih1  = (const float*)d_in[3];
    const float* bih1  = (const float*)d_in[4];
    const float* Whh1  = (const float*)d_in[5];
    const float* bhh1  = (const float*)d_in[6];
    const float* Wih2  = (const float*)d_in[7];
    const float* bih2  = (const float*)d_in[8];
    const float* Whh2  = (const float*)d_in[9];
    const float* bhh2  = (const float*)d_in[10];
    const float* Wq    = (const float*)d_in[11];
    const float* bq    = (const float*)d_in[12];
    const float* Wk    = (const float*)d_in[13];
    const float* bk    = (const float*)d_in[14];
    const float* Wv    = (const float*)d_in[15];
    const float* bv    = (const float*)d_in[16];
    const float* W1    = (const float*)d_in[17];
    const float* b1    = (const float*)d_in[18];
    const float* bcls  = (const float*)d_in[19];

    float* outL = (float*)d_out;
    long long need = (long long)Bc * Tc * Vc + (long long)Bc * Tc * Sc;

    float* attnB; int attnBS, attnTS;
    if ((long long)out_size >= need) {
        attnB = outL + (size_t)Bc * Tc * Vc;
        attnBS = Tc * Sc; attnTS = Sc;
    } else {
        cudaGetSymbolAddress((void**)&attnB, g_attn_dummy);
        attnBS = Sc; attnTS = 0;
    }

    cudaFuncSetAttribute(decoder_kernel,
                         cudaFuncAttributeMaxDynamicSharedMemorySize, SMEM_BYTES);

    decoder_kernel<<<NBLK, NTHR, SMEM_BYTES>>>(enc, y, Wemb, Wih1, bih1, Whh1, bhh1,
                                               Wih2, bih2, Whh2, bhh2, Wq, bq, Wk, bk,
                                               Wv, bv, W1, b1, bcls, outL,
                                               attnB, attnBS, attnTS);
}

// round 9
// speedup vs baseline: 4.4284x; 1.0434x over previous
#include <cuda_runtime.h>
#include <cuda_fp16.h>
#include <math.h>

#define Bc  64
#define Sc  512
#define Tc  256
#define Ec  512
#define Hc  512
#define KQc 256
#define Vc  1000
#define BH  (Bc*Hc)
#define NBLK 128
#define NTHR 512

typedef unsigned long long u64t;

// ---------------- dynamic smem layout (float offsets) ----------------
#define OFF_W0    0                      // A-blocks: Whh1 32x516 ; B-blocks: Wemb 16x516
#define OFF_WL2H  16512                  // Whh2 16x516
#define OFF_WL2X  24768                  // Wih2 16x516
#define OFF_WHID  33024                  // W1 4x1028 (full K=1024)
#define OFF_AB    37136                  // A double buffer 2x64x68 (aliased by attn)
#define OFF_RED   45840                  // reduction 128x66
#define OFF_SS    (OFF_RED + 8320)      // 128 merge scales (inside RED tail, PD-only)
#define SMEM_F    54288
#define SMEM_BYTES (SMEM_F * 4)          // 217152 B

// ---------------- device scratch ----------------
__device__ float  g_ktmp[(size_t)Bc*Sc*KQc];   // K fp32 (precompute temp)
__device__ __half g_kk[(size_t)Bc*Sc*Ec];      // KK = K @ Wq  [B*S, 512] fp16
__device__ float  g_c0[(size_t)Bc*Sc];         // bq . k
__device__ __half g_vh[(size_t)Bc*Sc*Ec];      // V cache fp16
__device__ float  g_emb1[(size_t)Vc*4*Hc];     // token -> LSTM1 x-side gate preacts
__device__ float  g_h1[2*BH], g_c1[2*BH], g_h2[2*BH], g_c2[2*BH];
__device__ float  g_ctxp[2*(size_t)Bc*Ec];     // split-KV ctx partials [half][b][e]
__device__ float2 g_mz[2*Bc];                  // per (b,half): {m_local, Z_local}
__device__ float  g_hid[Bc*Hc];
__device__ float  g_attn_dummy[Bc*Sc];

// ---------------- grid barrier ----------------
__device__ volatile unsigned g_flags[NBLK*32];
__device__ volatile unsigned g_release;

__device__ __forceinline__ void gsync(unsigned gen) {
    __syncthreads();
    if (blockIdx.x == 0) {
        int tid = threadIdx.x;
        if (tid > 0 && tid < NBLK)
            while (g_flags[tid * 32] < gen) { }
        __syncthreads();
        if (tid == 0) { __threadfence(); g_release = gen; }
    } else {
        if (threadIdx.x == 0) {
            __threadfence();
            g_flags[blockIdx.x * 32] = gen;
            while (g_release < gen) { }
            __threadfence();
        }
    }
    __syncthreads();
}

// ---------------- f32x2 packed FMA ----------------
__device__ __forceinline__ u64t fma2(u64t a, u64t b, u64t c) {
    u64t d;
    asm("fma.rn.f32x2 %0, %1, %2, %3;" : "=l"(d) : "l"(a), "l"(b), "l"(c));
    return d;
}
__device__ __forceinline__ float hsum2(u64t v) {
    return __uint_as_float((unsigned)v) + __uint_as_float((unsigned)(v >> 32));
}

// ---------------- GEMM core (broadcast-W, lane=batch, k-split) ----------------
template<int NROWS, int NRPT>
__device__ __forceinline__ void mm_chunk2(u64t (*acc)[2], const float* __restrict__ wch,
                                          int padw, const float* __restrict__ ab) {
    const int NRG = NROWS / NRPT;
    const int NKH = 16 / NRG;
    const int KPT = 64 / NKH;
    int warp = threadIdx.x >> 5, lane = threadIdx.x & 31;
    int rg = warp % NRG;
    int kh = warp / NRG;
    int k0 = kh * KPT;
    const float* wbase = wch + (rg * NRPT) * padw + k0;
    const float* a0 = ab + lane * 68 + k0;
    const float* a1 = ab + (lane + 32) * 68 + k0;
    #pragma unroll
    for (int kk = 0; kk < KPT; kk += 4) {
        ulonglong2 A0 = *(const ulonglong2*)(a0 + kk);
        ulonglong2 A1 = *(const ulonglong2*)(a1 + kk);
        #pragma unroll
        for (int r = 0; r < NRPT; r++) {
            ulonglong2 W = *(const ulonglong2*)(wbase + r * padw + kk);
            acc[r][0] = fma2(A0.x, W.x, acc[r][0]);
            acc[r][1] = fma2(A1.x, W.x, acc[r][1]);
            acc[r][0] = fma2(A0.y, W.y, acc[r][0]);
            acc[r][1] = fma2(A1.y, W.y, acc[r][1]);
        }
    }
}

template<int NROWS, int NRPT, int NCH>
__device__ void gemm_stream2(u64t (*acc)[2], const float* __restrict__ A0,
                             const float* __restrict__ wsm, int padw, float* sm) {
    float* b0f = sm + OFF_AB;
    float* b1f = b0f + 64 * 68;
    int tid = threadIdx.x;
    int row0 = tid >> 4, c4 = (tid & 15) * 4;
    int row1 = row0 + 32;
    *(float4*)&b0f[row0 * 68 + c4] = *(const float4*)&A0[(size_t)row0 * 512 + c4];
    *(float4*)&b0f[row1 * 68 + c4] = *(const float4*)&A0[(size_t)row1 * 512 + c4];
    __syncthreads();
    #pragma unroll
    for (int i = 0; i < NCH; i++) {
        float* cur = (i & 1) ? b1f : b0f;
        float* nxt = (i & 1) ? b0f : b1f;
        float4 p0, p1;
        if (i + 1 < NCH) {
            p0 = *(const float4*)&A0[(size_t)row0 * 512 + (i + 1) * 64 + c4];
            p1 = *(const float4*)&A0[(size_t)row1 * 512 + (i + 1) * 64 + c4];
        }
        mm_chunk2<NROWS, NRPT>(acc, wsm + i * 64, padw, cur);
        if (i + 1 < NCH) {
            *(float4*)&nxt[row0 * 68 + c4] = p0;
            *(float4*)&nxt[row1 * 68 + c4] = p1;
        }
        __syncthreads();
    }
}

// ctx stream with split-KV combine inline: A = sS0*ctxp0 + sS1*ctxp1
__device__ void gemm_stream_ctx(u64t (*acc)[2], const float* __restrict__ wsm, float* sm) {
    float* b0f = sm + OFF_AB;
    float* b1f = b0f + 64 * 68;
    const float* sS = sm + OFF_SS;
    int tid = threadIdx.x;
    int row0 = tid >> 4, c4 = (tid & 15) * 4;
    int row1 = row0 + 32;
    float s00 = sS[2 * row0], s01 = sS[2 * row0 + 1];
    float s10 = sS[2 * row1], s11 = sS[2 * row1 + 1];
    const float* cp0 = g_ctxp;
    const float* cp1 = g_ctxp + (size_t)Bc * Ec;
    #pragma unroll
    for (int q = 0; q < 4; q++) {
        float a0 = cp0[(size_t)row0 * 512 + c4 + q] * s00 + cp1[(size_t)row0 * 512 + c4 + q] * s01;
        float a1 = cp0[(size_t)row1 * 512 + c4 + q] * s10 + cp1[(size_t)row1 * 512 + c4 + q] * s11;
        b0f[row0 * 68 + c4 + q] = a0;
        b1f[row1 * 68 + c4 + q] = a1;   // temp misuse avoided below
    }
    // fix: both rows into b0f
    #pragma unroll
    for (int q = 0; q < 4; q++)
        b0f[row1 * 68 + c4 + q] = b1f[row1 * 68 + c4 + q];
    __syncthreads();
    #pragma unroll
    for (int i = 0; i < 8; i++) {
        float* cur = (i & 1) ? b1f : b0f;
        float* nxt = (i & 1) ? b0f : b1f;
        float p0[4], p1[4];
        if (i + 1 < 8) {
            int off = (i + 1) * 64 + c4;
            #pragma unroll
            for (int q = 0; q < 4; q++) {
                p0[q] = cp0[(size_t)row0 * 512 + off + q] * s00 + cp1[(size_t)row0 * 512 + off + q] * s01;
                p1[q] = cp0[(size_t)row1 * 512 + off + q] * s10 + cp1[(size_t)row1 * 512 + off + q] * s11;
            }
        }
        mm_chunk2<4, 4>(acc, wsm + i * 64, 1028, cur);
        if (i + 1 < 8) {
            #pragma unroll
            for (int q = 0; q < 4; q++) {
                nxt[row0 * 68 + c4 + q] = p0[q];
                nxt[row1 * 68 + c4 + q] = p1[q];
            }
        }
        __syncthreads();
    }
}

template<int NROWS, int NRPT>
__device__ __forceinline__ void red_write2(u64t (*acc)[2], float* red) {
    const int NRG = NROWS / NRPT;
    int warp = threadIdx.x >> 5, lane = threadIdx.x & 31;
    int rg = warp % NRG, kh = warp / NRG;
    #pragma unroll
    for (int r = 0; r < NRPT; r++) {
        int rr = kh * NROWS + rg * NRPT + r;
        red[rr * 66 + lane]      = hsum2(acc[r][0]);
        red[rr * 66 + lane + 32] = hsum2(acc[r][1]);
    }
}

// ---------------- LSTM1: 64 blocks, 32 rows (8 j) each ----------------
__device__ void lstm1_phase(const float* __restrict__ hin, const float* __restrict__ cin,
                            float* __restrict__ hout, float* __restrict__ cout,
                            const int* __restrict__ y, int t, float* sm) {
    int tile = blockIdx.x;                     // 0..63 ; j = tile*8 + jj
    u64t acc[8][2] = {};
    gemm_stream2<32, 8, 8>(acc, hin, sm + OFF_W0, 516, sm);
    float* red = sm + OFF_RED;
    red_write2<32, 8>(acc, red);
    __syncthreads();
    int u = threadIdx.x;
    int jj = u & 7, b = u >> 3;
    int j = tile * 8 + jj;
    float p[4] = {0.f, 0.f, 0.f, 0.f};
    #pragma unroll
    for (int kh = 0; kh < 4; kh++)
        #pragma unroll
        for (int g = 0; g < 4; g++)
            p[g] += red[(kh * 32 + g * 8 + jj) * 66 + b];
    int tok = (t == 0) ? 0 : y[b * Tc + t - 1];
    const float* e = g_emb1 + (size_t)tok * (4 * Hc);
    p[0] += e[j]; p[1] += e[Hc + j]; p[2] += e[2 * Hc + j]; p[3] += e[3 * Hc + j];
    float si = 1.f / (1.f + __expf(-p[0]));
    float sf = 1.f / (1.f + __expf(-p[1]));
    float so = 1.f / (1.f + __expf(-p[3]));
    float cN = sf * cin[b * Hc + j] + si * tanhf(p[2]);
    float hN = so * tanhf(cN);
    hout[b * Hc + j] = hN;
    cout[b * Hc + j] = cN;
}

// ---------------- LSTM2: all blocks, 16 rows (4 j) ----------------
__device__ void lstm2_phase(const float* __restrict__ hin, const float* __restrict__ cin,
                            float* __restrict__ hout, float* __restrict__ cout,
                            const float* __restrict__ xsrc,
                            const float* __restrict__ bih, const float* __restrict__ bhh,
                            float* sm) {
    int tile = blockIdx.x;                     // j = tile*4 + jj
    u64t acc[8][2] = {};
    gemm_stream2<16, 8, 8>(acc, hin,  sm + OFF_WL2H, 516, sm);
    gemm_stream2<16, 8, 8>(acc, xsrc, sm + OFF_WL2X, 516, sm);
    float* red = sm + OFF_RED;
    red_write2<16, 8>(acc, red);
    __syncthreads();
    int u = threadIdx.x;
    if (u < 256) {
        int jj = u & 3, b = u >> 2;
        int j = tile * 4 + jj;
        float p[4] = {0.f, 0.f, 0.f, 0.f};
        #pragma unroll
        for (int kh = 0; kh < 8; kh++)
            #pragma unroll
            for (int g = 0; g < 4; g++)
                p[g] += red[(kh * 16 + g * 4 + jj) * 66 + b];
        p[0] += bih[j]          + bhh[j];
        p[1] += bih[Hc + j]     + bhh[Hc + j];
        p[2] += bih[2 * Hc + j] + bhh[2 * Hc + j];
        p[3] += bih[3 * Hc + j] + bhh[3 * Hc + j];
        float si = 1.f / (1.f + __expf(-p[0]));
        float sf = 1.f / (1.f + __expf(-p[1]));
        float so = 1.f / (1.f + __expf(-p[3]));
        float cN = sf * cin[b * Hc + j] + si * tanhf(p[2]);
        float hN = so * tanhf(cN);
        hout[b * Hc + j] = hN;
        cout[b * Hc + j] = cN;
    }
}

// ---------------- attention: split-KV, 2 blocks per batch ----------------
struct AttnS {
    float qh[512];
    float scl[256];
    float ctxp[3 * 512];
    float red[16];
    float red2[16];
};

__device__ __forceinline__ float dot8h(const float* qr, uint4 pk) {
    const __half2* p2 = (const __half2*)&pk;
    float s = 0.f;
    #pragma unroll
    for (int q = 0; q < 4; q++) {
        float2 f = __half22float2(p2[q]);
        s += qr[q * 2] * f.x + qr[q * 2 + 1] * f.y;
    }
    return s;
}

__device__ void attn_phase(const float* __restrict__ h2n, float* __restrict__ attn_half,
                           float* sm) {
    int pairb = blockIdx.x >> 1, half = blockIdx.x & 1;
    AttnS* at = (AttnS*)(sm + OFF_AB);
    int tid = threadIdx.x, warp = tid >> 5, lane = tid & 31;
    int s0 = half * 256;

    at->qh[tid] = h2n[pairb * Hc + tid];
    __syncthreads();

    float hr[16];
    #pragma unroll
    for (int u2 = 0; u2 < 16; u2++) hr[u2] = at->qh[lane * 16 + u2];

    // scores over this half: sc = (h2 . KK[b,s] + c0[b,s]) * scale
    #pragma unroll
    for (int i = 0; i < 8; i++) {
        int sA = s0 + warp + i * 32, sB = sA + 16;
        const __half* ka = g_kk + ((size_t)(pairb * Sc + sA)) * Ec + lane * 16;
        const __half* kb = g_kk + ((size_t)(pairb * Sc + sB)) * Ec + lane * 16;
        float sa = dot8h(hr, *(const uint4*)ka) + dot8h(hr + 8, *(const uint4*)(ka + 8));
        float sb = dot8h(hr, *(const uint4*)kb) + dot8h(hr + 8, *(const uint4*)(kb + 8));
        #pragma unroll
        for (int o = 16; o; o >>= 1) {
            sa += __shfl_down_sync(~0u, sa, o);
            sb += __shfl_down_sync(~0u, sb, o);
        }
        if (lane == 0) {
            at->scl[sA - s0] = (sa + g_c0[pairb * Sc + sA]) * 0.0625f;
            at->scl[sB - s0] = (sb + g_c0[pairb * Sc + sB]) * 0.0625f;
        }
    }
    __syncthreads();

    // local softmax partials over 256
    float v = (tid < 256) ? at->scl[tid] : -3.0e38f;
    float m = v;
    #pragma unroll
    for (int o = 16; o; o >>= 1) m = fmaxf(m, __shfl_xor_sync(~0u, m, o));
    if (lane == 0) at->red[warp] = m;
    __syncthreads();
    float mm = at->red[0];
    #pragma unroll
    for (int w = 1; w < 8; w++) mm = fmaxf(mm, at->red[w]);
    float e = (tid < 256) ? __expf(v - mm) : 0.f;
    float ssum = e;
    #pragma unroll
    for (int o = 16; o; o >>= 1) ssum += __shfl_xor_sync(~0u, ssum, o);
    if (lane == 0) at->red2[warp] = ssum;
    __syncthreads();
    if (tid == 0) {
        float Z = 0.f;
        #pragma unroll
        for (int w = 0; w < 16; w++) Z += at->red2[w];
        g_mz[pairb * 2 + half] = make_float2(mm, Z);
    }
    if (tid < 256) {
        at->scl[tid] = e;
        attn_half[tid] = e;              // unnormalized; rescaled in PD
    }
    __syncthreads();

    // partial ctx over this half (fp16 V), 4-way s-split
    int sq = tid >> 7;
    int e4 = (tid & 127) * 4;
    const __half* vb = g_vh + (size_t)pairb * Sc * Ec + e4;
    float a0 = 0.f, a1 = 0.f, a2 = 0.f, a3 = 0.f;
    int sb2 = sq * 64;
    #pragma unroll 8
    for (int i2 = 0; i2 < 64; i2++) {
        float pp = at->scl[sb2 + i2];
        uint2 pk = *(const uint2*)(vb + (size_t)(s0 + sb2 + i2) * Ec);
        float2 f0 = __half22float2(*(__half2*)&pk.x);
        float2 f1 = __half22float2(*(__half2*)&pk.y);
        a0 += pp * f0.x; a1 += pp * f0.y; a2 += pp * f1.x; a3 += pp * f1.y;
    }
    if (sq) {
        float* cp = at->ctxp + (sq - 1) * 512 + e4;
        cp[0] = a0; cp[1] = a1; cp[2] = a2; cp[3] = a3;
    }
    __syncthreads();
    if (sq == 0) {
        #pragma unroll
        for (int q = 0; q < 3; q++) {
            const float* cp = at->ctxp + q * 512 + e4;
            a0 += cp[0]; a1 += cp[1]; a2 += cp[2]; a3 += cp[3];
        }
        float4 o = {a0, a1, a2, a3};
        *(float4*)&g_ctxp[(size_t)half * Bc * Ec + pairb * Ec + e4] = o;
    }
}

// ---------------- hid phase: merge scales + rescale attn + hid GEMM ----------------
__device__ void hid_phase(const float* __restrict__ h2n, const float* __restrict__ b1,
                          float* __restrict__ attn_half, float* sm) {
    float* sS = sm + OFF_SS;
    int tid = threadIdx.x;
    if (tid < 128) {
        int bb = tid >> 1, h = tid & 1;
        float2 mz0 = g_mz[bb * 2 + 0];
        float2 mz1 = g_mz[bb * 2 + 1];
        float m = fmaxf(mz0.x, mz1.x);
        float Z = mz0.y * __expf(mz0.x - m) + mz1.y * __expf(mz1.x - m);
        float mh = h ? mz1.x : mz0.x;
        sS[tid] = __expf(mh - m) / Z;
    }
    __syncthreads();
    // rescale this block's attn half to final probabilities
    {
        float f = sS[blockIdx.x];
        if (tid < 256) attn_half[tid] *= f;
    }
    u64t acc[4][2] = {};
    gemm_stream2<4, 4, 8>(acc, h2n, sm + OFF_WHID, 1028, sm);
    gemm_stream_ctx(acc, sm + OFF_WHID + 512, sm);
    float* red = sm + OFF_RED;
    red_write2<4, 4>(acc, red);
    __syncthreads();
    int u = threadIdx.x;
    if (u < 256) {
        int r = u & 3, b = u >> 2;
        int j = blockIdx.x * 4 + r;
        float sum = b1[j];
        #pragma unroll
        for (int kh = 0; kh < 16; kh++) sum += red[(kh * 4 + r) * 66 + b];
        g_hid[(size_t)b * Hc + j] = fmaxf(sum, 0.f);
    }
}

// ---------------- logits: B-blocks, 16 rows each ----------------
__device__ void logits_phase(const float* __restrict__ bcls, float* __restrict__ outL,
                             int t, float* sm) {
    int tile = blockIdx.x - 64;                // 0..63
    u64t acc[8][2] = {};
    gemm_stream2<16, 8, 8>(acc, g_hid, sm + OFF_W0, 516, sm);
    float* red = sm + OFF_RED;
    red_write2<16, 8>(acc, red);
    __syncthreads();
    int u = threadIdx.x;
    int r = u & 15, b0 = (u >> 4) * 2;
    int j = tile * 16 + r;
    if (j < Vc) {
        float s0 = bcls[j], s1 = bcls[j];
        #pragma unroll
        for (int kh = 0; kh < 8; kh++) {
            s0 += red[(kh * 16 + r) * 66 + b0];
            s1 += red[(kh * 16 + r) * 66 + b0 + 1];
        }
        outL[((size_t)b0 * Tc + t) * Vc + j]       = s0;
        outL[((size_t)(b0 + 1) * Tc + t) * Vc + j] = s1;
    }
}

// ---------------- weight preload ----------------
__device__ void preload_weights(float* sm, const float* __restrict__ Whh1,
                                const float* __restrict__ Whh2, const float* __restrict__ Wih2,
                                const float* __restrict__ W1, const float* __restrict__ Wemb) {
    int tid = threadIdx.x;
    int tile = blockIdx.x;
    if (tile < 64) {
        for (int i = tid; i < 32 * 128; i += NTHR) {       // Whh1 32 rows
            int r = i >> 7, c4 = (i & 127) * 4;
            int srow = (r >> 3) * Hc + tile * 8 + (r & 7);
            *(float4*)&sm[OFF_W0 + r * 516 + c4] = *(const float4*)&Whh1[(size_t)srow * Hc + c4];
        }
    } else {
        int tl = tile - 64;
        for (int i = tid; i < 16 * 128; i += NTHR) {       // Wemb 16 rows
            int r = i >> 7, c4 = (i & 127) * 4;
            int srow = tl * 16 + r; if (srow >= Vc) srow = Vc - 1;
            *(float4*)&sm[OFF_W0 + r * 516 + c4] = *(const float4*)&Wemb[(size_t)srow * Hc + c4];
        }
    }
    for (int i = tid; i < 16 * 128; i += NTHR) {
        int r = i >> 7, c4 = (i & 127) * 4;
        int srow = (r >> 2) * Hc + tile * 4 + (r & 3);
        *(float4*)&sm[OFF_WL2H + r * 516 + c4] = *(const float4*)&Whh2[(size_t)srow * Hc + c4];
        *(float4*)&sm[OFF_WL2X + r * 516 + c4] = *(const float4*)&Wih2[(size_t)srow * Hc + c4];
    }
    for (int i = tid; i < 4 * 256; i += NTHR) {
        int r = i >> 8, c4 = (i & 255) * 4;
        *(float4*)&sm[OFF_WHID + r * 1028 + c4] =
            *(const float4*)&W1[(size_t)(tile * 4 + r) * (Hc + Ec) + c4];
    }
}

// ---------------- precompute 64x64 GEMM tile ----------------
__device__ __forceinline__ void storeC(float* C, size_t idx, float v) { C[idx] = v; }
__device__ __forceinline__ void storeC(__half* C, size_t idx, float v) { C[idx] = __float2half(v); }

template<bool WT, class OUT>
__device__ void gemm_tile(const float* __restrict__ A, const float* __restrict__ W,
                          const float* __restrict__ b1v, const float* __restrict__ b2v,
                          OUT* __restrict__ C, int M, int N, int K, int m0, int n0, float* sm) {
    float* As = sm + OFF_AB;
    float* Ws = As + 16 * 68;
    int tid = threadIdx.x;
    int tx = tid & 15, ty = tid >> 4;
    float acc[2][4] = {};
    for (int kb = 0; kb < K; kb += 16) {
        __syncthreads();
        #pragma unroll
        for (int u2 = 0; u2 < 2; u2++) {
            int i = tid + u2 * NTHR;
            int r = i >> 4, kk = i & 15;
            int ra = m0 + r; if (ra >= M) ra = M - 1;
            As[kk * 68 + r] = A[(size_t)ra * K + kb + kk];
            Ws[kk * 68 + r] = WT ? W[(size_t)(kb + kk) * N + n0 + r]
                                 : W[(size_t)(n0 + r) * K + kb + kk];
        }
        __syncthreads();
        #pragma unroll
        for (int kk = 0; kk < 16; kk++) {
            float a0 = As[kk * 68 + ty * 2];
            float a1 = As[kk * 68 + ty * 2 + 1];
            float4 w4 = *(const float4*)&Ws[kk * 68 + tx * 4];
            float wr[4] = {w4.x, w4.y, w4.z, w4.w};
            #pragma unroll
            for (int jv = 0; jv < 4; jv++) {
                acc[0][jv] += a0 * wr[jv];
                acc[1][jv] += a1 * wr[jv];
            }
        }
    }
    __syncthreads();
    #pragma unroll
    for (int i = 0; i < 2; i++) {
        int row = m0 + ty * 2 + i;
        if (row < M) {
            #pragma unroll
            for (int jv = 0; jv < 4; jv++) {
                int col = n0 + tx * 4 + jv;
                float vv = acc[i][jv];
                if (b1v) vv += b1v[col];
                if (b2v) vv += b2v[col];
                storeC(C, (size_t)row * N + col, vv);
            }
        }
    }
}

// ---------------- persistent kernel ----------------
__global__ void __launch_bounds__(NTHR, 1)
decoder_kernel(const float* __restrict__ enc, const int* __restrict__ y,
               const float* __restrict__ Wemb,
               const float* __restrict__ Wih1, const float* __restrict__ bih1,
               const float* __restrict__ Whh1, const float* __restrict__ bhh1,
               const float* __restrict__ Wih2, const float* __restrict__ bih2,
               const float* __restrict__ Whh2, const float* __restrict__ bhh2,
               const float* __restrict__ Wq,  const float* __restrict__ bq,
               const float* __restrict__ Wk,  const float* __restrict__ bk,
               const float* __restrict__ Wv,  const float* __restrict__ bv,
               const float* __restrict__ W1,  const float* __restrict__ b1,
               const float* __restrict__ bcls,
               float* __restrict__ outL, float* __restrict__ attnB,
               int attnBS, int attnTS)
{
    extern __shared__ float sm[];
    int tid = threadIdx.x;
    unsigned gen = g_release;

    for (int i = blockIdx.x * NTHR + tid; i < BH; i += NBLK * NTHR) {
        g_h1[i] = 0.f; g_c1[i] = 0.f; g_h2[i] = 0.f; g_c2[i] = 0.f;
    }
    preload_weights(sm, Whh1, Whh2, Wih2, W1, Wemb);
    gsync(++gen);

    // pre1: K fp32 (temp), V fp16, LSTM1 token table
    {
        const int nKt = (Bc * Sc / 64) * (KQc / 64);
        const int nVt = (Bc * Sc / 64) * (Ec / 64);
        const int nEt = 16 * (4 * Hc / 64);
        for (int idx = blockIdx.x; idx < nKt + nVt + nEt; idx += NBLK) {
            if (idx < nKt) {
                int m0 = (idx / (KQc / 64)) * 64, n0 = (idx % (KQc / 64)) * 64;
                gemm_tile<false>(enc, Wk, bk, (const float*)0, g_ktmp,
                                 Bc * Sc, KQc, Ec, m0, n0, sm);
            } else if (idx < nKt + nVt) {
                int i2 = idx - nKt;
                int m0 = (i2 / (Ec / 64)) * 64, n0 = (i2 % (Ec / 64)) * 64;
                gemm_tile<false>(enc, Wv, bv, (const float*)0, g_vh,
                                 Bc * Sc, Ec, Ec, m0, n0, sm);
            } else {
                int i2 = idx - nKt - nVt;
                int m0 = (i2 / 32) * 64, n0 = (i2 % 32) * 64;
                gemm_tile<false>(Wemb, Wih1, bih1, bhh1, g_emb1,
                                 Vc, 4 * Hc, Hc, m0, n0, sm);
            }
        }
    }
    gsync(++gen);

    // pre2: KK = K @ Wq (fp16) and c0 = K . bq
    {
        const int nT = (Bc * Sc / 64) * (Ec / 64);     // 4096
        for (int idx = blockIdx.x; idx < nT; idx += NBLK) {
            int m0 = (idx / (Ec / 64)) * 64, n0 = (idx % (Ec / 64)) * 64;
            gemm_tile<true>(g_ktmp, Wq, (const float*)0, (const float*)0, g_kk,
                            Bc * Sc, Ec, KQc, m0, n0, sm);
        }
        int lane = tid & 31;
        int gw = (blockIdx.x * NTHR + tid) >> 5;
        float bqr[8];
        #pragma unroll
        for (int q = 0; q < 8; q++) bqr[q] = bq[lane * 8 + q];
        for (int m = gw; m < Bc * Sc; m += (NBLK * NTHR) >> 5) {
            const float* kr = g_ktmp + (size_t)m * KQc + lane * 8;
            float4 k0 = *(const float4*)kr;
            float4 k1 = *(const float4*)(kr + 4);
            float s = bqr[0]*k0.x + bqr[1]*k0.y + bqr[2]*k0.z + bqr[3]*k0.w
                    + bqr[4]*k1.x + bqr[5]*k1.y + bqr[6]*k1.z + bqr[7]*k1.w;
            #pragma unroll
            for (int o = 16; o; o >>= 1) s += __shfl_down_sync(~0u, s, o);
            if (lane == 0) g_c0[m] = s;
        }
    }
    gsync(++gen);

    int pairb = blockIdx.x >> 1, half = blockIdx.x & 1;

    for (int t = 0; t < Tc; t++) {
        int cur = t & 1, nxt = cur ^ 1;

        // PA: LSTM1 (blocks 0..63) || logits(t-1) (blocks 64..127)
        if (blockIdx.x < 64)
            lstm1_phase(g_h1 + cur * BH, g_c1 + cur * BH,
                        g_h1 + nxt * BH, g_c1 + nxt * BH, y, t, sm);
        else if (t > 0)
            logits_phase(bcls, outL, t - 1, sm);
        gsync(++gen);

        // PB: LSTM2 (all blocks)
        lstm2_phase(g_h2 + cur * BH, g_c2 + cur * BH,
                    g_h2 + nxt * BH, g_c2 + nxt * BH,
                    g_h1 + nxt * BH, bih2, bhh2, sm);
        gsync(++gen);

        // PC: split-KV attention (all blocks; 2 per batch)
        {
            float* ah = attnB + (size_t)pairb * attnBS + (size_t)t * attnTS + half * 256;
            attn_phase(g_h2 + nxt * BH, ah, sm);
        }
        gsync(++gen);

        // PD: merge + rescale attn + hid
        {
            float* ah = attnB + (size_t)pairb * attnBS + (size_t)t * attnTS + half * 256;
            hid_phase(g_h2 + nxt * BH, b1, ah, sm);
        }
        gsync(++gen);
    }

    // final logits for t = Tc-1
    if (blockIdx.x >= 64)
        logits_phase(bcls, outL, Tc - 1, sm);
}

// ---------------- launch ----------------
extern "C" void kernel_launch(void* const* d_in, const int* in_sizes, int n_in,
                              void* d_out, int out_size) {
    const float* enc   = (const float*)d_in[0];
    const int*   y     = (const int*)  d_in[1];
    const float* Wemb  = (const float*)d_in[2];
    const float* Wih1  = (const float*)d_in[3];
    const float* bih1  = (const float*)d_in[4];
    const float* Whh1  = (const float*)d_in[5];
    const float* bhh1  = (const float*)d_in[6];
    const float* Wih2  = (const float*)d_in[7];
    const float* bih2  = (const float*)d_in[8];
    const float* Whh2  = (const float*)d_in[9];
    const float* bhh2  = (const float*)d_in[10];
    const float* Wq    = (const float*)d_in[11];
    const float* bq    = (const float*)d_in[12];
    const float* Wk    = (const float*)d_in[13];
    const float* bk    = (const float*)d_in[14];
    const float* Wv    = (const float*)d_in[15];
    const float* bv    = (const float*)d_in[16];
    const float* W1    = (const float*)d_in[17];
    const float* b1    = (const float*)d_in[18];
    const float* bcls  = (const float*)d_in[19];

    float* outL = (float*)d_out;
    long long need = (long long)Bc * Tc * Vc + (long long)Bc * Tc * Sc;

    float* attnB; int attnBS, attnTS;
    if ((long long)out_size >= need) {
        attnB = outL + (size_t)Bc * Tc * Vc;
        attnBS = Tc * Sc; attnTS = Sc;
    } else {
        cudaGetSymbolAddress((void**)&attnB, g_attn_dummy);
        attnBS = Sc; attnTS = 0;
    }

    cudaFuncSetAttribute(decoder_kernel,
                         cudaFuncAttributeMaxDynamicSharedMemorySize, SMEM_BYTES);

    decoder_kernel<<<NBLK, NTHR, SMEM_BYTES>>>(enc, y, Wemb, Wih1, bih1, Whh1, bhh1,
                                               Wih2, bih2, Whh2, bhh2, Wq, bq, Wk, bk,
                                               Wv, bv, W1, b1, bcls, outL,
                                               attnB, attnBS, attnTS);
}